// round 14
// baseline (speedup 1.0000x reference)
#include <cuda_runtime.h>
#include <cuda_bf16.h>
#include <cuda_fp16.h>
#include <math.h>
#include <stdint.h>

#define N_NODES 25000
#define N_EDGES 400000
#define HDIM 128

// ---- device scratch (no allocations allowed) ----
__device__ __half g_xh[N_NODES * 384];   // interaction MLP output, fp16
__device__ __half g_vh[N_NODES * 384];   // v copy, fp16 (for gathers)
__device__ __half g_oh[N_NODES * 384];   // mixing MLP output, fp16
__device__ float g_vw[N_NODES * 3 * 256];
__device__ float g_dot[N_NODES * 128];
__device__ uint32_t g_hhi [N_NODES * 64];
__device__ uint32_t g_hlo [N_NODES * 64];
__device__ uint32_t g_tshi[N_NODES * 128];
__device__ uint32_t g_tslo[N_NODES * 128];
__device__ uint32_t g_hmhi[N_NODES * 64];
__device__ uint32_t g_hmlo[N_NODES * 64];
__device__ int    g_cnt[N_NODES];
__device__ int    g_off[N_NODES + 1];
__device__ int    g_cur[N_NODES];
__device__ float4 g_edir[N_EDGES];   // CSR-ordered {d0,d1,d2, bitcast(e)}
__device__ int    g_ercv[N_EDGES];   // CSR-ordered receiver
__device__ int    g_bsum[32];
// transposed bf16 hi/lo weights: [N][K] layout per weight
// Wi1@0 (K128,N128) Wi2@16384 (128,384) Wm1@65536 (256,128) Wm2@98304 (128,384) Wv@147456 (128,256)
__device__ __nv_bfloat16 g_whi[180224];
__device__ __nv_bfloat16 g_wlo[180224];

__device__ __forceinline__ float silu_f(float x) { return x / (1.0f + __expf(-x)); }
__device__ __forceinline__ float clip100(float x) { return fminf(fmaxf(x, -100.0f), 100.0f); }

__device__ __forceinline__ float4 f4z() { float4 r; r.x=r.y=r.z=r.w=0.f; return r; }
__device__ __forceinline__ float4 f4fma(float a, float4 b, float4 c) {
    c.x = fmaf(a, b.x, c.x); c.y = fmaf(a, b.y, c.y);
    c.z = fmaf(a, b.z, c.z); c.w = fmaf(a, b.w, c.w); return c;
}
__device__ __forceinline__ float4 f4mul(float4 a, float4 b) {
    float4 r; r.x=a.x*b.x; r.y=a.y*b.y; r.z=a.z*b.z; r.w=a.w*b.w; return r;
}
__device__ __forceinline__ float4 f4fma4(float4 a, float4 b, float4 c) {
    c.x = fmaf(a.x, b.x, c.x); c.y = fmaf(a.y, b.y, c.y);
    c.z = fmaf(a.z, b.z, c.z); c.w = fmaf(a.w, b.w, c.w); return c;
}
__device__ __forceinline__ float4 f4add(float4 a, float4 b) {
    float4 r; r.x=a.x+b.x; r.y=a.y+b.y; r.z=a.z+b.z; r.w=a.w+b.w; return r;
}
__device__ __forceinline__ float4 f4clip(float4 a) {
    float4 r; r.x=clip100(a.x); r.y=clip100(a.y); r.z=clip100(a.z); r.w=clip100(a.w); return r;
}
// load 4 consecutive halfs (8B) -> float4
__device__ __forceinline__ float4 h4_to_f4(const __half2* p) {
    uint2 u = *(const uint2*)p;
    __half2 a = *(__half2*)&u.x;
    __half2 b = *(__half2*)&u.y;
    float2 fa = __half22float2(a);
    float2 fb = __half22float2(b);
    float4 r; r.x = fa.x; r.y = fa.y; r.z = fb.x; r.w = fb.y;
    return r;
}

__device__ __forceinline__ uint32_t smem_u32(const void* p) {
    uint32_t a;
    asm("{ .reg .u64 tmp; cvta.to.shared.u64 tmp, %1; cvt.u32.u64 %0, tmp; }"
        : "=r"(a) : "l"(p));
    return a;
}
__device__ __forceinline__ uint32_t cvt_bf2(float a, float b) {
    uint32_t r;
    asm("cvt.rn.bf16x2.f32 %0, %1, %2;" : "=r"(r) : "f"(b), "f"(a));
    return r;
}
__device__ __forceinline__ void split2(float a, float b, uint32_t& h, uint32_t& l) {
    h = cvt_bf2(a, b);
    float r0 = a - __uint_as_float(h << 16);
    float r1 = b - __uint_as_float(h & 0xFFFF0000u);
    l = cvt_bf2(r0, r1);
}
__device__ __forceinline__ void ldsm_x4(uint32_t* r, uint32_t addr) {
    asm volatile("ldmatrix.sync.aligned.m8n8.x4.shared.b16 {%0,%1,%2,%3}, [%4];"
                 : "=r"(r[0]), "=r"(r[1]), "=r"(r[2]), "=r"(r[3]) : "r"(addr));
}
__device__ __forceinline__ void mma_bf16(float* d, const uint32_t* a, uint32_t b0, uint32_t b1) {
    asm volatile("mma.sync.aligned.m16n8k16.row.col.f32.bf16.bf16.f32 "
        "{%0,%1,%2,%3}, {%4,%5,%6,%7}, {%8,%9}, {%0,%1,%2,%3};"
        : "+f"(d[0]), "+f"(d[1]), "+f"(d[2]), "+f"(d[3])
        : "r"(a[0]), "r"(a[1]), "r"(a[2]), "r"(a[3]), "r"(b0), "r"(b1));
}
#define SW128(o) ((o) ^ (((o) >> 3) & 0x70))

// one 64-k chunk of MMAs over 128x128 tile (split-bf16 3-product)
__device__ __forceinline__ void mma_chunk(
    uint32_t sb, uint32_t ahi_off, uint32_t alo_off, uint32_t bhi_off, uint32_t blo_off,
    int a_row, int a_atom, int b_row, int b_atom, float acc[2][8][4])
{
#pragma unroll
    for (int ks = 0; ks < 4; ks++) {
        uint32_t ahi[2][4], alo[2][4];
#pragma unroll
        for (int mt = 0; mt < 2; mt++) {
            uint32_t off = SW128((uint32_t)((a_row + mt * 16) * 128 + (ks * 2 + a_atom) * 16));
            ldsm_x4(ahi[mt], sb + ahi_off + off);
            ldsm_x4(alo[mt], sb + alo_off + off);
        }
#pragma unroll
        for (int j = 0; j < 4; j++) {
            uint32_t offb = SW128((uint32_t)((b_row + j * 16) * 128 + (ks * 2 + b_atom) * 16));
            uint32_t bh[4], bl[4];
            ldsm_x4(bh, sb + bhi_off + offb);
            ldsm_x4(bl, sb + blo_off + offb);
#pragma unroll
            for (int mt = 0; mt < 2; mt++) {
                mma_bf16(acc[mt][2*j],   ahi[mt], bh[0], bh[1]);
                mma_bf16(acc[mt][2*j],   alo[mt], bh[0], bh[1]);
                mma_bf16(acc[mt][2*j],   ahi[mt], bl[0], bl[1]);
                mma_bf16(acc[mt][2*j+1], ahi[mt], bh[2], bh[3]);
                mma_bf16(acc[mt][2*j+1], alo[mt], bh[2], bh[3]);
                mma_bf16(acc[mt][2*j+1], ahi[mt], bl[2], bl[3]);
            }
        }
    }
}

// ============================================================
// Weight pre-convert: W[K,N] fp32 -> Wt[N][K] bf16 hi/lo
// ============================================================
__global__ void k_convW(const float* __restrict__ W0, const float* __restrict__ W1,
                        const float* __restrict__ W2, const float* __restrict__ W3,
                        const float* __restrict__ W4) {
    const float* srcs[5] = {W0, W1, W2, W3, W4};
    const int Ks[5]   = {128, 128, 256, 128, 128};
    const int Ns[5]   = {128, 384, 128, 384, 256};
    const int offs[5] = {0, 16384, 65536, 98304, 147456};
    int w = blockIdx.y;
    const float* W = srcs[w];
    int K = Ks[w], N = Ns[w], off = offs[w];
    int total = K * N;
    for (int idx = blockIdx.x * blockDim.x + threadIdx.x; idx < total;
         idx += gridDim.x * blockDim.x) {
        int n = idx / K, k = idx - n * K;
        float v = W[k * N + n];
        __nv_bfloat16 h = __float2bfloat16(v);
        float r = v - __bfloat162float(h);
        g_whi[off + idx] = h;
        g_wlo[off + idx] = __float2bfloat16(r);
    }
}

// v fp32 -> fp16 copy (for message gathers)
__global__ void k_convV(const float* __restrict__ v) {
    long i = (long)blockIdx.x * blockDim.x + threadIdx.x;
    if (i >= (long)N_NODES * 96) return;
    float4 a = ((const float4*)v)[i];
    __half2 h0 = __floats2half2_rn(a.x, a.y);
    __half2 h1 = __floats2half2_rn(a.z, a.w);
    uint2 u;
    u.x = *(uint32_t*)&h0;
    u.y = *(uint32_t*)&h1;
    *(uint2*)(g_vh + i * 4) = u;
}

// ============================================================
// General split-bf16 mma.sync GEMM (R8-proven). Used for the two
// square (N=128) layers: s->h and ts->hm.
// OSPLIT: 1 = packed bf16 hi/lo output (chi/clo)
// ============================================================
#define MG_OFF_AHI   0
#define MG_OFF_ALO   16384
#define MG_OFF_BHI   32768
#define MG_OFF_BLO   49152
#define MG_SMEM_TOTAL 65536

template<int EPI, int ASPLIT>
__global__ __launch_bounds__(256, 2)
void k_mgemm(const float* __restrict__ A,
             const __nv_bfloat16* __restrict__ ahi_g, const __nv_bfloat16* __restrict__ alo_g,
             int woff, const float* __restrict__ bias,
             uint32_t* __restrict__ chi, uint32_t* __restrict__ clo,
             int M, int N, int K)
{
    extern __shared__ char smem[];
    const uint32_t sb = smem_u32(smem);

    const int t = threadIdx.x;
    const int lane = t & 31;
    const int wid = t >> 5;
    const int warp_m = wid & 3;
    const int warp_n = wid >> 2;
    const int m0 = blockIdx.x * 128;
    const int n0 = blockIdx.y * 128;

    const __nv_bfloat16* bhg = g_whi + woff;
    const __nv_bfloat16* blg = g_wlo + woff;

    float acc[2][8][4];
#pragma unroll
    for (int i = 0; i < 2; i++)
#pragma unroll
        for (int j = 0; j < 8; j++)
#pragma unroll
            for (int q = 0; q < 4; q++) acc[i][j][q] = 0.f;

    const int a_row  = warp_m * 32 + (lane & 15);
    const int a_atom = lane >> 4;
    const int b_row  = warp_n * 64 + (lane & 7) + ((lane & 16) ? 8 : 0);
    const int b_atom = (lane >> 3) & 1;

    const int nchunk = K >> 6;
    for (int c = 0; c < nchunk; c++) {
        const int k0 = c << 6;
        if (ASPLIT) {
#pragma unroll
            for (int i = 0; i < 4; i++) {
                int idx = t + i * 256;
                int row = idx >> 3;
                int kq  = idx & 7;
                uint4 h = make_uint4(0,0,0,0), l = make_uint4(0,0,0,0);
                if (m0 + row < M) {
                    long ga = (long)(m0 + row) * K + k0 + kq * 8;
                    h = *(const uint4*)(ahi_g + ga);
                    l = *(const uint4*)(alo_g + ga);
                }
                uint32_t off = SW128((uint32_t)(row * 128 + kq * 16));
                *(uint4*)(smem + MG_OFF_AHI + off) = h;
                *(uint4*)(smem + MG_OFF_ALO + off) = l;
            }
        } else {
#pragma unroll
            for (int i = 0; i < 8; i++) {
                int idx = t + i * 256;
                int row = idx >> 4;
                int kq  = idx & 15;
                float4 a = f4z();
                if (m0 + row < M) a = *(const float4*)(A + (long)(m0 + row) * K + k0 + kq * 4);
                uint32_t h0, l0, h1, l1;
                split2(a.x, a.y, h0, l0);
                split2(a.z, a.w, h1, l1);
                uint32_t off = SW128((uint32_t)(row * 128 + kq * 8));
                *(uint2*)(smem + MG_OFF_AHI + off) = make_uint2(h0, h1);
                *(uint2*)(smem + MG_OFF_ALO + off) = make_uint2(l0, l1);
            }
        }
#pragma unroll
        for (int i = 0; i < 4; i++) {
            int idx = t + i * 256;
            int row = idx >> 3;
            int kq  = idx & 7;
            long ga = (long)(n0 + row) * K + k0 + kq * 8;
            uint4 h = *(const uint4*)(bhg + ga);
            uint4 l = *(const uint4*)(blg + ga);
            uint32_t off = SW128((uint32_t)(row * 128 + kq * 16));
            *(uint4*)(smem + MG_OFF_BHI + off) = h;
            *(uint4*)(smem + MG_OFF_BLO + off) = l;
        }
        __syncthreads();
        mma_chunk(sb, MG_OFF_AHI, MG_OFF_ALO, MG_OFF_BHI, MG_OFF_BLO,
                  a_row, a_atom, b_row, b_atom, acc);
        __syncthreads();
    }

    const int g   = lane >> 2;
    const int tg2 = (lane & 3) * 2;
#pragma unroll
    for (int mt = 0; mt < 2; mt++) {
        int row = m0 + warp_m * 32 + mt * 16 + g;
#pragma unroll
        for (int nt = 0; nt < 8; nt++) {
            int col = n0 + warp_n * 64 + nt * 8 + tg2;
            float d0 = acc[mt][nt][0], d1 = acc[mt][nt][1];
            float d2 = acc[mt][nt][2], d3 = acc[mt][nt][3];
            if (EPI > 0) {
                float b0 = bias[col], b1 = bias[col + 1];
                d0 += b0; d1 += b1; d2 += b0; d3 += b1;
            }
            if (EPI == 2) {
                d0 = silu_f(d0); d1 = silu_f(d1); d2 = silu_f(d2); d3 = silu_f(d3);
            }
            if (row < M) {
                uint32_t h, l; split2(d0, d1, h, l);
                long hx = ((long)row * N + col) >> 1;
                chi[hx] = h; clo[hx] = l;
            }
            if (row + 8 < M) {
                uint32_t h, l; split2(d2, d3, h, l);
                long hx = ((long)(row + 8) * N + col) >> 1;
                chi[hx] = h; clo[hx] = l;
            }
        }
    }
}

// ============================================================
// N-loop GEMM (A resident): C[M,384] = Asplit[M,128] @ W[128,384] + bias,
// fp16 output. A (bf16 hi/lo) loaded once; 3 N-blocks over one B buffer.
// 96KB smem, occupancy 2.  (k_vw-pattern, R8-proven)
// ============================================================
#define M3_AHI(kc) ((kc) * 16384)
#define M3_ALO(kc) (32768 + (kc) * 16384)
#define M3_BHI 65536
#define M3_BLO 81920
#define M3_SMEM_TOTAL 98304

__global__ __launch_bounds__(256, 2)
void k_mgemm3(const __nv_bfloat16* __restrict__ ahi_g, const __nv_bfloat16* __restrict__ alo_g,
              int woff, const float* __restrict__ bias,
              __half* __restrict__ C, int M)
{
    const int K = 128;
    extern __shared__ char smem[];
    const uint32_t sb = smem_u32(smem);

    const int t = threadIdx.x;
    const int lane = t & 31;
    const int wid = t >> 5;
    const int warp_m = wid & 3;
    const int warp_n = wid >> 2;
    const int m0 = blockIdx.x * 128;

    const __nv_bfloat16* bhg = g_whi + woff;
    const __nv_bfloat16* blg = g_wlo + woff;

    const int a_row  = warp_m * 32 + (lane & 15);
    const int a_atom = lane >> 4;
    const int b_row  = warp_n * 64 + (lane & 7) + ((lane & 16) ? 8 : 0);
    const int b_atom = (lane >> 3) & 1;

    // ---- load full A (K=128 bf16 hi/lo) once ----
#pragma unroll
    for (int i = 0; i < 8; i++) {
        int idx = t + i * 256;          // 0..2047
        int row = idx >> 4;             // 0..127
        int kq4 = idx & 15;             // uint4 group over 128 bf16
        int kc  = kq4 >> 3;
        int kq  = kq4 & 7;
        uint4 h = make_uint4(0,0,0,0), l = make_uint4(0,0,0,0);
        if (m0 + row < M) {
            long ga = (long)(m0 + row) * K + kq4 * 8;
            h = *(const uint4*)(ahi_g + ga);
            l = *(const uint4*)(alo_g + ga);
        }
        uint32_t off = SW128((uint32_t)(row * 128 + kq * 16));
        *(uint4*)(smem + M3_AHI(kc) + off) = h;
        *(uint4*)(smem + M3_ALO(kc) + off) = l;
    }
    __syncthreads();

    const int g   = lane >> 2;
    const int tg2 = (lane & 3) * 2;

#pragma unroll
    for (int nb = 0; nb < 3; nb++) {
        float acc[2][8][4];
#pragma unroll
        for (int i = 0; i < 2; i++)
#pragma unroll
            for (int j = 0; j < 8; j++)
#pragma unroll
                for (int q = 0; q < 4; q++) acc[i][j][q] = 0.f;

#pragma unroll
        for (int kc = 0; kc < 2; kc++) {
            if (!(nb == 0 && kc == 0)) __syncthreads();
#pragma unroll
            for (int i = 0; i < 4; i++) {
                int idx = t + i * 256;
                int row = idx >> 3;
                int kq  = idx & 7;
                long ga = (long)(nb * 128 + row) * K + kc * 64 + kq * 8;
                uint4 h = *(const uint4*)(bhg + ga);
                uint4 l = *(const uint4*)(blg + ga);
                uint32_t off = SW128((uint32_t)(row * 128 + kq * 16));
                *(uint4*)(smem + M3_BHI + off) = h;
                *(uint4*)(smem + M3_BLO + off) = l;
            }
            __syncthreads();
            mma_chunk(sb, M3_AHI(kc), M3_ALO(kc), M3_BHI, M3_BLO,
                      a_row, a_atom, b_row, b_atom, acc);
        }
        // epilogue (registers only)
#pragma unroll
        for (int mt = 0; mt < 2; mt++) {
            int row = m0 + warp_m * 32 + mt * 16 + g;
#pragma unroll
            for (int nt = 0; nt < 8; nt++) {
                int colg = nb * 128 + warp_n * 64 + nt * 8 + tg2;
                float b0 = bias[colg], b1 = bias[colg + 1];
                if (row < M) {
                    __half2 o = __floats2half2_rn(acc[mt][nt][0] + b0, acc[mt][nt][1] + b1);
                    *(__half2*)(C + (long)row * 384 + colg) = o;
                }
                if (row + 8 < M) {
                    __half2 o = __floats2half2_rn(acc[mt][nt][2] + b0, acc[mt][nt][3] + b1);
                    *(__half2*)(C + (long)(row + 8) * 384 + colg) = o;
                }
            }
        }
    }
}

// ============================================================
// vw GEMM: C[75000,256] = out_v[75000,128] @ Wv (R8-proven)
// ============================================================
#define VW_AHI(kc) ((kc) * 16384)
#define VW_ALO(kc) (32768 + (kc) * 16384)
#define VW_BHI 65536
#define VW_BLO 81920
#define VW_SMEM_TOTAL 98304

__global__ __launch_bounds__(256, 2)
void k_vw(const float* __restrict__ A, float* __restrict__ C)
{
    const int M = N_NODES * 3, K = 128, N = 256;
    extern __shared__ char smem[];
    const uint32_t sb = smem_u32(smem);

    const int t = threadIdx.x;
    const int lane = t & 31;
    const int wid = t >> 5;
    const int warp_m = wid & 3;
    const int warp_n = wid >> 2;
    const int m0 = blockIdx.x * 128;

    const __nv_bfloat16* bhg = g_whi + 147456;
    const __nv_bfloat16* blg = g_wlo + 147456;

    const int a_row  = warp_m * 32 + (lane & 15);
    const int a_atom = lane >> 4;
    const int b_row  = warp_n * 64 + (lane & 7) + ((lane & 16) ? 8 : 0);
    const int b_atom = (lane >> 3) & 1;

#pragma unroll
    for (int i = 0; i < 16; i++) {
        int idx = t + i * 256;
        int row = idx >> 5;
        int kq4 = idx & 31;
        int kc  = kq4 >> 4;
        int kq  = kq4 & 15;
        float4 a = f4z();
        if (m0 + row < M) a = *(const float4*)(A + (long)(m0 + row) * K + kq4 * 4);
        uint32_t h0, l0, h1, l1;
        split2(a.x, a.y, h0, l0);
        split2(a.z, a.w, h1, l1);
        uint32_t off = SW128((uint32_t)(row * 128 + kq * 8));
        *(uint2*)(smem + VW_AHI(kc) + off) = make_uint2(h0, h1);
        *(uint2*)(smem + VW_ALO(kc) + off) = make_uint2(l0, l1);
    }
    __syncthreads();

    const int g   = lane >> 2;
    const int tg2 = (lane & 3) * 2;

#pragma unroll
    for (int nh = 0; nh < 2; nh++) {
        float acc[2][8][4];
#pragma unroll
        for (int i = 0; i < 2; i++)
#pragma unroll
            for (int j = 0; j < 8; j++)
#pragma unroll
                for (int q = 0; q < 4; q++) acc[i][j][q] = 0.f;

#pragma unroll
        for (int kc = 0; kc < 2; kc++) {
            if (!(nh == 0 && kc == 0)) __syncthreads();
#pragma unroll
            for (int i = 0; i < 4; i++) {
                int idx = t + i * 256;
                int row = idx >> 3;
                int kq  = idx & 7;
                long ga = (long)(nh * 128 + row) * K + kc * 64 + kq * 8;
                uint4 h = *(const uint4*)(bhg + ga);
                uint4 l = *(const uint4*)(blg + ga);
                uint32_t off = SW128((uint32_t)(row * 128 + kq * 16));
                *(uint4*)(smem + VW_BHI + off) = h;
                *(uint4*)(smem + VW_BLO + off) = l;
            }
            __syncthreads();
            mma_chunk(sb, VW_AHI(kc), VW_ALO(kc), VW_BHI, VW_BLO,
                      a_row, a_atom, b_row, b_atom, acc);
        }
#pragma unroll
        for (int mt = 0; mt < 2; mt++) {
            int row = m0 + warp_m * 32 + mt * 16 + g;
#pragma unroll
            for (int nt = 0; nt < 8; nt++) {
                int col = nh * 128 + warp_n * 64 + nt * 8 + tg2;
                if (row < M) {
                    float2 o; o.x = acc[mt][nt][0]; o.y = acc[mt][nt][1];
                    *(float2*)(C + (long)row * N + col) = o;
                }
                if (row + 8 < M) {
                    float2 o; o.x = acc[mt][nt][2]; o.y = acc[mt][nt][3];
                    *(float2*)(C + (long)(row + 8) * N + col) = o;
                }
            }
        }
    }
}

// ============================================================
// CSR build by sender
// ============================================================
__global__ void k_count(const int* __restrict__ senders) {
    int e = blockIdx.x * blockDim.x + threadIdx.x;
    if (e < N_EDGES) atomicAdd(&g_cnt[senders[e]], 1);
}
__global__ void k_scanA() {
    __shared__ int sm[1024];
    int t = threadIdx.x;
    int i = blockIdx.x * 1024 + t;
    int v = (i < N_NODES) ? g_cnt[i] : 0;
    sm[t] = v;
    __syncthreads();
    for (int off = 1; off < 1024; off <<= 1) {
        int x = (t >= off) ? sm[t - off] : 0;
        __syncthreads();
        sm[t] += x;
        __syncthreads();
    }
    if (i < N_NODES) g_off[i] = sm[t] - v;
    if (t == 1023) g_bsum[blockIdx.x] = sm[1023];
}
__global__ void k_scanC() {
    __shared__ int pre_sh;
    if (threadIdx.x == 0) {
        int p = 0;
        for (int b = 0; b < blockIdx.x; b++) p += g_bsum[b];
        pre_sh = p;
        if (blockIdx.x == gridDim.x - 1) g_off[N_NODES] = p + g_bsum[blockIdx.x];
    }
    __syncthreads();
    int pre = pre_sh;
    int i = blockIdx.x * 1024 + threadIdx.x;
    if (i < N_NODES) {
        int o = g_off[i] + pre;
        g_off[i] = o;
        g_cur[i] = o;
    }
}
__global__ void k_fill(const int* __restrict__ senders, const int* __restrict__ receivers,
                       const float* __restrict__ dir_ij) {
    int e = blockIdx.x * blockDim.x + threadIdx.x;
    if (e < N_EDGES) {
        int p = atomicAdd(&g_cur[senders[e]], 1);
        float4 ed;
        ed.x = dir_ij[e * 3 + 0];
        ed.y = dir_ij[e * 3 + 1];
        ed.z = dir_ij[e * 3 + 2];
        ed.w = __int_as_float(e);
        g_edir[p] = ed;
        g_ercv[p] = receivers[e];
    }
}

// ============================================================
// Message gather-reduce: TWO warps per node (even/odd edge split).
// Wij evict-first; x/v gathered fp16. Partials combined via smem.
// ============================================================
__global__ void k_message(const float* __restrict__ s, const float* __restrict__ v,
                          const float* __restrict__ Wij,
                          float* __restrict__ out_s, float* __restrict__ out_v) {
    __shared__ float4 red[4][32][4];
    int gw   = (blockIdx.x * blockDim.x + threadIdx.x) >> 5;
    int node = gw >> 1;
    int half = gw & 1;
    int lane = threadIdx.x & 31;
    int pair = (threadIdx.x >> 6);
    if (node >= N_NODES) return;

    float4 ds  = f4z();
    float4 dv0 = f4z(), dv1 = f4z(), dv2 = f4z();

    int beg = g_off[node], end = g_off[node + 1];
    for (int i = beg + half; i < end; i += 2) {
        float4 ed = g_edir[i];
        int r = g_ercv[i];
        int e = __float_as_int(ed.w);
        const float4*  we = (const float4*)(Wij + (long)e * 384);
        const __half2* xr = (const __half2*)g_xh + (long)r * 192;
        const __half2* vr = (const __half2*)g_vh + (long)r * 192;

        float4 w0 = __ldcs(we + lane);
        float4 w1 = __ldcs(we + 32 + lane);
        float4 w2 = __ldcs(we + 64 + lane);
        float4 x0 = h4_to_f4(xr + lane * 2);
        float4 x1 = h4_to_f4(xr + 64 + lane * 2);
        float4 x2 = h4_to_f4(xr + 128 + lane * 2);

        ds = f4fma4(w0, x0, ds);
        float4 m1 = f4mul(w1, x1);
        float4 m2 = f4mul(w2, x2);

        float4 vj0 = h4_to_f4(vr + lane * 2);
        float4 vj1 = h4_to_f4(vr + 64 + lane * 2);
        float4 vj2 = h4_to_f4(vr + 128 + lane * 2);
        dv0 = f4fma(ed.x, m1, dv0); dv0 = f4fma4(m2, vj0, dv0);
        dv1 = f4fma(ed.y, m1, dv1); dv1 = f4fma4(m2, vj1, dv1);
        dv2 = f4fma(ed.z, m1, dv2); dv2 = f4fma4(m2, vj2, dv2);
    }

    if (half == 1) {
        red[pair][lane][0] = ds;
        red[pair][lane][1] = dv0;
        red[pair][lane][2] = dv1;
        red[pair][lane][3] = dv2;
    }
    __syncthreads();
    if (half == 0) {
        ds  = f4add(ds,  red[pair][lane][0]);
        dv0 = f4add(dv0, red[pair][lane][1]);
        dv1 = f4add(dv1, red[pair][lane][2]);
        dv2 = f4add(dv2, red[pair][lane][3]);

        float4 s4 = ((const float4*)(s + node * HDIM))[lane];
        ((float4*)(out_s + node * HDIM))[lane] = f4add(s4, f4clip(ds));

        const float4* vi = (const float4*)(v + (long)node * 384);
        float4* vo = (float4*)(out_v + (long)node * 384);
        vo[lane]      = f4add(vi[lane],      f4clip(dv0));
        vo[32 + lane] = f4add(vi[32 + lane], f4clip(dv1));
        vo[64 + lane] = f4add(vi[64 + lane], f4clip(dv2));
    }
}

// ============================================================
// Build ts (pre-split bf16 hi/lo) and dot
// ============================================================
__global__ void k_ts(const float* __restrict__ out_s) {
    long idx = (long)blockIdx.x * blockDim.x + threadIdx.x;
    if (idx >= (long)N_NODES * 32) return;
    int n  = (int)(idx >> 5);
    int c4 = (int)(idx & 31);
    const float4* vw = (const float4*)(g_vw + (long)n * 768) + c4;
    float4 vl0 = vw[0],   vr0 = vw[32];
    float4 vl1 = vw[64],  vr1 = vw[96];
    float4 vl2 = vw[128], vr2 = vw[160];
    float4 vn;
    vn.x = sqrtf(vr0.x*vr0.x + vr1.x*vr1.x + vr2.x*vr2.x + 1e-8f);
    vn.y = sqrtf(vr0.y*vr0.y + vr1.y*vr1.y + vr2.y*vr2.y + 1e-8f);
    vn.z = sqrtf(vr0.z*vr0.z + vr1.z*vr1.z + vr2.z*vr2.z + 1e-8f);
    vn.w = sqrtf(vr0.w*vr0.w + vr1.w*vr1.w + vr2.w*vr2.w + 1e-8f);

    float4 sv = ((const float4*)(out_s + (long)n * 128))[c4];
    long hb = (long)n * 128 + c4 * 2;
    uint32_t h0, l0, h1, l1;
    split2(sv.x, sv.y, h0, l0);
    split2(sv.z, sv.w, h1, l1);
    *(uint2*)(g_tshi + hb) = make_uint2(h0, h1);
    *(uint2*)(g_tslo + hb) = make_uint2(l0, l1);
    split2(vn.x, vn.y, h0, l0);
    split2(vn.z, vn.w, h1, l1);
    *(uint2*)(g_tshi + hb + 64) = make_uint2(h0, h1);
    *(uint2*)(g_tslo + hb + 64) = make_uint2(l0, l1);

    float4 dt;
    dt.x = vr0.x*vl0.x + vr1.x*vl1.x + vr2.x*vl2.x;
    dt.y = vr0.y*vl0.y + vr1.y*vl1.y + vr2.y*vl2.y;
    dt.z = vr0.z*vl0.z + vr1.z*vl1.z + vr2.z*vl2.z;
    dt.w = vr0.w*vl0.w + vr1.w*vl1.w + vr2.w*vl2.w;
    ((float4*)g_dot)[idx] = dt;
}

// ============================================================
// Final epilogue (reads O as fp16)
// ============================================================
__global__ void k_final(float* __restrict__ out_s, float* __restrict__ out_v) {
    long idx = (long)blockIdx.x * blockDim.x + threadIdx.x;
    if (idx >= (long)N_NODES * 32) return;
    int n  = (int)(idx >> 5);
    int c4 = (int)(idx & 31);
    const __half2* O = (const __half2*)(g_oh + (long)n * 384);
    float4 o0 = h4_to_f4(O + c4 * 2);
    float4 o1 = h4_to_f4(O + 64 + c4 * 2);
    float4 o2 = h4_to_f4(O + 128 + c4 * 2);
    float4 dot = ((const float4*)g_dot)[idx];
    float4 sacc = ((float4*)out_s)[idx];
    sacc.x += clip100(fmaf(o2.x, dot.x, o0.x));
    sacc.y += clip100(fmaf(o2.y, dot.y, o0.y));
    sacc.z += clip100(fmaf(o2.z, dot.z, o0.z));
    sacc.w += clip100(fmaf(o2.w, dot.w, o0.w));
    ((float4*)out_s)[idx] = sacc;
    const float4* vw = (const float4*)(g_vw + (long)n * 768);
    float4* vv = (float4*)(out_v + (long)n * 384);
#pragma unroll
    for (int d = 0; d < 3; d++) {
        float4 vl = vw[d * 64 + c4];
        float4 acc = vv[d * 32 + c4];
        acc.x += clip100(vl.x * o1.x);
        acc.y += clip100(vl.y * o1.y);
        acc.z += clip100(vl.z * o1.z);
        acc.w += clip100(vl.w * o1.w);
        vv[d * 32 + c4] = acc;
    }
}

// ============================================================
extern "C" void kernel_launch(void* const* d_in, const int* in_sizes, int n_in,
                              void* d_out, int out_size) {
    const float* s   = (const float*)d_in[0];
    const float* v   = (const float*)d_in[1];
    const float* dir = (const float*)d_in[2];
    const float* Wij = (const float*)d_in[3];
    const float* Wi1 = (const float*)d_in[4];
    const float* bi1 = (const float*)d_in[5];
    const float* Wi2 = (const float*)d_in[6];
    const float* bi2 = (const float*)d_in[7];
    const float* Wm1 = (const float*)d_in[8];
    const float* bm1 = (const float*)d_in[9];
    const float* Wm2 = (const float*)d_in[10];
    const float* bm2 = (const float*)d_in[11];
    const float* Wv  = (const float*)d_in[12];
    const int*   snd = (const int*)d_in[13];
    const int*   rcv = (const int*)d_in[14];

    float* out_s = (float*)d_out;
    float* out_v = (float*)d_out + (long)N_NODES * HDIM;

    float*    p_vw;   cudaGetSymbolAddress((void**)&p_vw,   g_vw);
    __half*   p_xh;   cudaGetSymbolAddress((void**)&p_xh,   g_xh);
    __half*   p_oh;   cudaGetSymbolAddress((void**)&p_oh,   g_oh);
    uint32_t* p_hhi;  cudaGetSymbolAddress((void**)&p_hhi,  g_hhi);
    uint32_t* p_hlo;  cudaGetSymbolAddress((void**)&p_hlo,  g_hlo);
    uint32_t* p_tshi; cudaGetSymbolAddress((void**)&p_tshi, g_tshi);
    uint32_t* p_tslo; cudaGetSymbolAddress((void**)&p_tslo, g_tslo);
    uint32_t* p_hmhi; cudaGetSymbolAddress((void**)&p_hmhi, g_hmhi);
    uint32_t* p_hmlo; cudaGetSymbolAddress((void**)&p_hmlo, g_hmlo);
    int*      p_cnt;  cudaGetSymbolAddress((void**)&p_cnt,  g_cnt);

    static cudaStream_t s2 = nullptr;
    static cudaEvent_t  e1 = nullptr, e2 = nullptr;
    if (!s2) {
        cudaStreamCreateWithFlags(&s2, cudaStreamNonBlocking);
        cudaEventCreateWithFlags(&e1, cudaEventDisableTiming);
        cudaEventCreateWithFlags(&e2, cudaEventDisableTiming);
        cudaFuncSetAttribute(k_mgemm<2,0>, cudaFuncAttributeMaxDynamicSharedMemorySize, MG_SMEM_TOTAL);
        cudaFuncSetAttribute(k_mgemm<2,1>, cudaFuncAttributeMaxDynamicSharedMemorySize, MG_SMEM_TOTAL);
        cudaFuncSetAttribute(k_mgemm3, cudaFuncAttributeMaxDynamicSharedMemorySize, M3_SMEM_TOTAL);
        cudaFuncSetAttribute(k_vw, cudaFuncAttributeMaxDynamicSharedMemorySize, VW_SMEM_TOTAL);
    }

    const int TPB = 256;
    int edge_blocks = (N_EDGES + TPB - 1) / TPB;
    int msg_blocks  = (int)(((long)N_NODES * 64 + TPB - 1) / TPB);
    int nc4_blocks = (int)(((long)N_NODES * 32 + TPB - 1) / TPB);
    int nv4_blocks = (int)(((long)N_NODES * 96 + TPB - 1) / TPB);
    const int MB  = (N_NODES + 127) / 128;        // 196
    const int MB3 = (N_NODES * 3 + 127) / 128;    // 586
    const int SCAN_BLK = (N_NODES + 1023) / 1024; // 25

    // ---- fork: v fp16 conv + CSR build on s2, concurrent with MLP GEMMs ----
    cudaEventRecord(e1, 0);
    cudaStreamWaitEvent(s2, e1, 0);
    k_convV<<<nv4_blocks, TPB, 0, s2>>>(v);
    cudaMemsetAsync(p_cnt, 0, N_NODES * sizeof(int), s2);
    k_count<<<edge_blocks, TPB, 0, s2>>>(snd);
    k_scanA<<<SCAN_BLK, 1024, 0, s2>>>();
    k_scanC<<<SCAN_BLK, 1024, 0, s2>>>();
    k_fill<<<edge_blocks, TPB, 0, s2>>>(snd, rcv, dir);
    cudaEventRecord(e2, s2);

    // ---- main stream: node MLP (h split, x fp16 via N-loop GEMM) ----
    k_convW<<<dim3(64, 5), TPB>>>(Wi1, Wi2, Wm1, Wm2, Wv);
    k_mgemm<2,0><<<dim3(MB, 1), 256, MG_SMEM_TOTAL>>>(
        s, (const __nv_bfloat16*)0, (const __nv_bfloat16*)0, 0, bi1,
        p_hhi, p_hlo, N_NODES, 128, 128);
    k_mgemm3<<<MB, 256, M3_SMEM_TOTAL>>>(
        (const __nv_bfloat16*)p_hhi, (const __nv_bfloat16*)p_hlo, 16384, bi2, p_xh, N_NODES);

    // ---- join, then message ----
    cudaStreamWaitEvent(0, e2, 0);
    k_message<<<msg_blocks, TPB>>>(s, v, Wij, out_s, out_v);

    // ---- update phase ----
    k_vw<<<MB3, 256, VW_SMEM_TOTAL>>>(out_v, p_vw);
    k_ts<<<nc4_blocks, TPB>>>(out_s);
    k_mgemm<2,1><<<dim3(MB, 1), 256, MG_SMEM_TOTAL>>>(
        (const float*)0, (const __nv_bfloat16*)p_tshi, (const __nv_bfloat16*)p_tslo, 65536, bm1,
        p_hmhi, p_hmlo, N_NODES, 128, 256);
    k_mgemm3<<<MB, 256, M3_SMEM_TOTAL>>>(
        (const __nv_bfloat16*)p_hmhi, (const __nv_bfloat16*)p_hmlo, 98304, bm2, p_oh, N_NODES);
    k_final<<<nc4_blocks, TPB>>>(out_s, out_v);
}

// round 15
// speedup vs baseline: 1.0465x; 1.0465x over previous
#include <cuda_runtime.h>
#include <cuda_bf16.h>
#include <cuda_fp16.h>
#include <math.h>
#include <stdint.h>

#define N_NODES 25000
#define N_EDGES 400000
#define HDIM 128

// ---- device scratch (no allocations allowed) ----
__device__ __half g_xh[N_NODES * 384];   // interaction MLP output, fp16
__device__ __half g_vh[N_NODES * 384];   // v copy, fp16 (for gathers)
__device__ float g_vw[N_NODES * 3 * 256];
__device__ float g_dot[N_NODES * 128];
__device__ float g_o [N_NODES * 384];
__device__ uint32_t g_hhi [N_NODES * 64];
__device__ uint32_t g_hlo [N_NODES * 64];
__device__ uint32_t g_tshi[N_NODES * 128];
__device__ uint32_t g_tslo[N_NODES * 128];
__device__ uint32_t g_hmhi[N_NODES * 64];
__device__ uint32_t g_hmlo[N_NODES * 64];
__device__ int    g_cnt[N_NODES];
__device__ int    g_off[N_NODES + 1];
__device__ int    g_cur[N_NODES];
__device__ float4 g_edir[N_EDGES];   // CSR-ordered {d0,d1,d2, bitcast(e)}
__device__ int    g_ercv[N_EDGES];   // CSR-ordered receiver
__device__ int    g_bsum[32];
// transposed bf16 hi/lo weights: [N][K] layout per weight
// Wi1@0 (K128,N128) Wi2@16384 (128,384) Wm1@65536 (256,128) Wm2@98304 (128,384) Wv@147456 (128,256)
__device__ __nv_bfloat16 g_whi[180224];
__device__ __nv_bfloat16 g_wlo[180224];

__device__ __forceinline__ float silu_f(float x) { return x / (1.0f + __expf(-x)); }
__device__ __forceinline__ float clip100(float x) { return fminf(fmaxf(x, -100.0f), 100.0f); }

__device__ __forceinline__ float4 f4z() { float4 r; r.x=r.y=r.z=r.w=0.f; return r; }
__device__ __forceinline__ float4 f4fma(float a, float4 b, float4 c) {
    c.x = fmaf(a, b.x, c.x); c.y = fmaf(a, b.y, c.y);
    c.z = fmaf(a, b.z, c.z); c.w = fmaf(a, b.w, c.w); return c;
}
__device__ __forceinline__ float4 f4mul(float4 a, float4 b) {
    float4 r; r.x=a.x*b.x; r.y=a.y*b.y; r.z=a.z*b.z; r.w=a.w*b.w; return r;
}
__device__ __forceinline__ float4 f4fma4(float4 a, float4 b, float4 c) {
    c.x = fmaf(a.x, b.x, c.x); c.y = fmaf(a.y, b.y, c.y);
    c.z = fmaf(a.z, b.z, c.z); c.w = fmaf(a.w, b.w, c.w); return c;
}
__device__ __forceinline__ float4 f4add(float4 a, float4 b) {
    float4 r; r.x=a.x+b.x; r.y=a.y+b.y; r.z=a.z+b.z; r.w=a.w+b.w; return r;
}
__device__ __forceinline__ float4 f4clip(float4 a) {
    float4 r; r.x=clip100(a.x); r.y=clip100(a.y); r.z=clip100(a.z); r.w=clip100(a.w); return r;
}
// load 4 consecutive halfs (8B) -> float4
__device__ __forceinline__ float4 h4_to_f4(const __half2* p) {
    uint2 u = *(const uint2*)p;
    __half2 a = *(__half2*)&u.x;
    __half2 b = *(__half2*)&u.y;
    float2 fa = __half22float2(a);
    float2 fb = __half22float2(b);
    float4 r; r.x = fa.x; r.y = fa.y; r.z = fb.x; r.w = fb.y;
    return r;
}

__device__ __forceinline__ uint32_t smem_u32(const void* p) {
    uint32_t a;
    asm("{ .reg .u64 tmp; cvta.to.shared.u64 tmp, %1; cvt.u32.u64 %0, tmp; }"
        : "=r"(a) : "l"(p));
    return a;
}
__device__ __forceinline__ uint32_t cvt_bf2(float a, float b) {
    uint32_t r;
    asm("cvt.rn.bf16x2.f32 %0, %1, %2;" : "=r"(r) : "f"(b), "f"(a));
    return r;
}
__device__ __forceinline__ void split2(float a, float b, uint32_t& h, uint32_t& l) {
    h = cvt_bf2(a, b);
    float r0 = a - __uint_as_float(h << 16);
    float r1 = b - __uint_as_float(h & 0xFFFF0000u);
    l = cvt_bf2(r0, r1);
}
__device__ __forceinline__ void ldsm_x4(uint32_t* r, uint32_t addr) {
    asm volatile("ldmatrix.sync.aligned.m8n8.x4.shared.b16 {%0,%1,%2,%3}, [%4];"
                 : "=r"(r[0]), "=r"(r[1]), "=r"(r[2]), "=r"(r[3]) : "r"(addr));
}
__device__ __forceinline__ void mma_bf16(float* d, const uint32_t* a, uint32_t b0, uint32_t b1) {
    asm volatile("mma.sync.aligned.m16n8k16.row.col.f32.bf16.bf16.f32 "
        "{%0,%1,%2,%3}, {%4,%5,%6,%7}, {%8,%9}, {%0,%1,%2,%3};"
        : "+f"(d[0]), "+f"(d[1]), "+f"(d[2]), "+f"(d[3])
        : "r"(a[0]), "r"(a[1]), "r"(a[2]), "r"(a[3]), "r"(b0), "r"(b1));
}
#define SW128(o) ((o) ^ (((o) >> 3) & 0x70))

// ============================================================
// Weight pre-convert: W[K,N] fp32 -> Wt[N][K] bf16 hi/lo
// ============================================================
__global__ void k_convW(const float* __restrict__ W0, const float* __restrict__ W1,
                        const float* __restrict__ W2, const float* __restrict__ W3,
                        const float* __restrict__ W4) {
    const float* srcs[5] = {W0, W1, W2, W3, W4};
    const int Ks[5]   = {128, 128, 256, 128, 128};
    const int Ns[5]   = {128, 384, 128, 384, 256};
    const int offs[5] = {0, 16384, 65536, 98304, 147456};
    int w = blockIdx.y;
    const float* W = srcs[w];
    int K = Ks[w], N = Ns[w], off = offs[w];
    int total = K * N;
    for (int idx = blockIdx.x * blockDim.x + threadIdx.x; idx < total;
         idx += gridDim.x * blockDim.x) {
        int n = idx / K, k = idx - n * K;
        float v = W[k * N + n];
        __nv_bfloat16 h = __float2bfloat16(v);
        float r = v - __bfloat162float(h);
        g_whi[off + idx] = h;
        g_wlo[off + idx] = __float2bfloat16(r);
    }
}

// v fp32 -> fp16 copy (for message gathers)
__global__ void k_convV(const float* __restrict__ v) {
    long i = (long)blockIdx.x * blockDim.x + threadIdx.x;   // over N*96 float4 groups
    if (i >= (long)N_NODES * 96) return;
    float4 a = ((const float4*)v)[i];
    __half2 h0 = __floats2half2_rn(a.x, a.y);
    __half2 h1 = __floats2half2_rn(a.z, a.w);
    uint2 u;
    u.x = *(uint32_t*)&h0;
    u.y = *(uint32_t*)&h1;
    *(uint2*)(g_vh + i * 4) = u;
}

// ============================================================
// General split-bf16 mma.sync GEMM (R8-proven).
// OSPLIT: 0 = fp32 C, 1 = packed bf16 hi/lo (chi/clo), 2 = fp16 (C cast to __half*)
// ============================================================
#define MG_OFF_AHI   0
#define MG_OFF_ALO   16384
#define MG_OFF_BHI   32768
#define MG_OFF_BLO   49152
#define MG_SMEM_TOTAL 65536

template<int EPI, int ASPLIT, int OSPLIT>
__global__ __launch_bounds__(256, 2)
void k_mgemm(const float* __restrict__ A,
             const __nv_bfloat16* __restrict__ ahi_g, const __nv_bfloat16* __restrict__ alo_g,
             int woff, const float* __restrict__ bias,
             float* __restrict__ C, uint32_t* __restrict__ chi, uint32_t* __restrict__ clo,
             int M, int N, int K)
{
    extern __shared__ char smem[];
    const uint32_t sb = smem_u32(smem);

    const int t = threadIdx.x;
    const int lane = t & 31;
    const int wid = t >> 5;
    const int warp_m = wid & 3;
    const int warp_n = wid >> 2;
    const int m0 = blockIdx.x * 128;
    const int n0 = blockIdx.y * 128;

    const __nv_bfloat16* bhg = g_whi + woff;
    const __nv_bfloat16* blg = g_wlo + woff;

    float acc[2][8][4];
#pragma unroll
    for (int i = 0; i < 2; i++)
#pragma unroll
        for (int j = 0; j < 8; j++)
#pragma unroll
            for (int q = 0; q < 4; q++) acc[i][j][q] = 0.f;

    const int a_row  = warp_m * 32 + (lane & 15);
    const int a_atom = lane >> 4;
    const int b_row  = warp_n * 64 + (lane & 7) + ((lane & 16) ? 8 : 0);
    const int b_atom = (lane >> 3) & 1;

    const int nchunk = K >> 6;
    for (int c = 0; c < nchunk; c++) {
        const int k0 = c << 6;
        if (ASPLIT) {
#pragma unroll
            for (int i = 0; i < 4; i++) {
                int idx = t + i * 256;
                int row = idx >> 3;
                int kq  = idx & 7;
                uint4 h = make_uint4(0,0,0,0), l = make_uint4(0,0,0,0);
                if (m0 + row < M) {
                    long ga = (long)(m0 + row) * K + k0 + kq * 8;
                    h = *(const uint4*)(ahi_g + ga);
                    l = *(const uint4*)(alo_g + ga);
                }
                uint32_t off = SW128((uint32_t)(row * 128 + kq * 16));
                *(uint4*)(smem + MG_OFF_AHI + off) = h;
                *(uint4*)(smem + MG_OFF_ALO + off) = l;
            }
        } else {
#pragma unroll
            for (int i = 0; i < 8; i++) {
                int idx = t + i * 256;
                int row = idx >> 4;
                int kq  = idx & 15;
                float4 a = f4z();
                if (m0 + row < M) a = *(const float4*)(A + (long)(m0 + row) * K + k0 + kq * 4);
                uint32_t h0, l0, h1, l1;
                split2(a.x, a.y, h0, l0);
                split2(a.z, a.w, h1, l1);
                uint32_t off = SW128((uint32_t)(row * 128 + kq * 8));
                *(uint2*)(smem + MG_OFF_AHI + off) = make_uint2(h0, h1);
                *(uint2*)(smem + MG_OFF_ALO + off) = make_uint2(l0, l1);
            }
        }
#pragma unroll
        for (int i = 0; i < 4; i++) {
            int idx = t + i * 256;
            int row = idx >> 3;
            int kq  = idx & 7;
            long ga = (long)(n0 + row) * K + k0 + kq * 8;
            uint4 h = *(const uint4*)(bhg + ga);
            uint4 l = *(const uint4*)(blg + ga);
            uint32_t off = SW128((uint32_t)(row * 128 + kq * 16));
            *(uint4*)(smem + MG_OFF_BHI + off) = h;
            *(uint4*)(smem + MG_OFF_BLO + off) = l;
        }
        __syncthreads();
#pragma unroll
        for (int ks = 0; ks < 4; ks++) {
            uint32_t ahi[2][4], alo[2][4];
#pragma unroll
            for (int mt = 0; mt < 2; mt++) {
                uint32_t off = SW128((uint32_t)((a_row + mt * 16) * 128 + (ks * 2 + a_atom) * 16));
                ldsm_x4(ahi[mt], sb + MG_OFF_AHI + off);
                ldsm_x4(alo[mt], sb + MG_OFF_ALO + off);
            }
#pragma unroll
            for (int j = 0; j < 4; j++) {
                uint32_t offb = SW128((uint32_t)((b_row + j * 16) * 128 + (ks * 2 + b_atom) * 16));
                uint32_t bh[4], bl[4];
                ldsm_x4(bh, sb + MG_OFF_BHI + offb);
                ldsm_x4(bl, sb + MG_OFF_BLO + offb);
#pragma unroll
                for (int mt = 0; mt < 2; mt++) {
                    mma_bf16(acc[mt][2*j],   ahi[mt], bh[0], bh[1]);
                    mma_bf16(acc[mt][2*j],   alo[mt], bh[0], bh[1]);
                    mma_bf16(acc[mt][2*j],   ahi[mt], bl[0], bl[1]);
                    mma_bf16(acc[mt][2*j+1], ahi[mt], bh[2], bh[3]);
                    mma_bf16(acc[mt][2*j+1], alo[mt], bh[2], bh[3]);
                    mma_bf16(acc[mt][2*j+1], ahi[mt], bl[2], bl[3]);
                }
            }
        }
        __syncthreads();
    }

    const int g   = lane >> 2;
    const int tg2 = (lane & 3) * 2;
#pragma unroll
    for (int mt = 0; mt < 2; mt++) {
        int row = m0 + warp_m * 32 + mt * 16 + g;
#pragma unroll
        for (int nt = 0; nt < 8; nt++) {
            int col = n0 + warp_n * 64 + nt * 8 + tg2;
            float d0 = acc[mt][nt][0], d1 = acc[mt][nt][1];
            float d2 = acc[mt][nt][2], d3 = acc[mt][nt][3];
            if (EPI > 0) {
                float b0 = bias[col], b1 = bias[col + 1];
                d0 += b0; d1 += b1; d2 += b0; d3 += b1;
            }
            if (EPI == 2) {
                d0 = silu_f(d0); d1 = silu_f(d1); d2 = silu_f(d2); d3 = silu_f(d3);
            }
            if (OSPLIT == 1) {
                if (row < M) {
                    uint32_t h, l; split2(d0, d1, h, l);
                    long hx = ((long)row * N + col) >> 1;
                    chi[hx] = h; clo[hx] = l;
                }
                if (row + 8 < M) {
                    uint32_t h, l; split2(d2, d3, h, l);
                    long hx = ((long)(row + 8) * N + col) >> 1;
                    chi[hx] = h; clo[hx] = l;
                }
            } else if (OSPLIT == 2) {
                __half* Ch = (__half*)C;
                if (row < M) {
                    __half2 o = __floats2half2_rn(d0, d1);
                    *(__half2*)(Ch + (long)row * N + col) = o;
                }
                if (row + 8 < M) {
                    __half2 o = __floats2half2_rn(d2, d3);
                    *(__half2*)(Ch + (long)(row + 8) * N + col) = o;
                }
            } else {
                if (row < M) {
                    float2 o; o.x = d0; o.y = d1;
                    *(float2*)(C + (long)row * N + col) = o;
                }
                if (row + 8 < M) {
                    float2 o; o.x = d2; o.y = d3;
                    *(float2*)(C + (long)(row + 8) * N + col) = o;
                }
            }
        }
    }
}

// ============================================================
// vw GEMM: C[75000,256] = out_v[75000,128] @ Wv (R8-proven)
// ============================================================
#define VW_AHI(kc) ((kc) * 16384)
#define VW_ALO(kc) (32768 + (kc) * 16384)
#define VW_BHI 65536
#define VW_BLO 81920
#define VW_SMEM_TOTAL 98304

__global__ __launch_bounds__(256, 2)
void k_vw(const float* __restrict__ A, float* __restrict__ C)
{
    const int M = N_NODES * 3, K = 128, N = 256;
    extern __shared__ char smem[];
    const uint32_t sb = smem_u32(smem);

    const int t = threadIdx.x;
    const int lane = t & 31;
    const int wid = t >> 5;
    const int warp_m = wid & 3;
    const int warp_n = wid >> 2;
    const int m0 = blockIdx.x * 128;

    const __nv_bfloat16* bhg = g_whi + 147456;
    const __nv_bfloat16* blg = g_wlo + 147456;

    const int a_row  = warp_m * 32 + (lane & 15);
    const int a_atom = lane >> 4;
    const int b_row  = warp_n * 64 + (lane & 7) + ((lane & 16) ? 8 : 0);
    const int b_atom = (lane >> 3) & 1;

#pragma unroll
    for (int i = 0; i < 16; i++) {
        int idx = t + i * 256;
        int row = idx >> 5;
        int kq4 = idx & 31;
        int kc  = kq4 >> 4;
        int kq  = kq4 & 15;
        float4 a = f4z();
        if (m0 + row < M) a = *(const float4*)(A + (long)(m0 + row) * K + kq4 * 4);
        uint32_t h0, l0, h1, l1;
        split2(a.x, a.y, h0, l0);
        split2(a.z, a.w, h1, l1);
        uint32_t off = SW128((uint32_t)(row * 128 + kq * 8));
        *(uint2*)(smem + VW_AHI(kc) + off) = make_uint2(h0, h1);
        *(uint2*)(smem + VW_ALO(kc) + off) = make_uint2(l0, l1);
    }
    __syncthreads();

    const int g   = lane >> 2;
    const int tg2 = (lane & 3) * 2;

#pragma unroll
    for (int nh = 0; nh < 2; nh++) {
        float acc[2][8][4];
#pragma unroll
        for (int i = 0; i < 2; i++)
#pragma unroll
            for (int j = 0; j < 8; j++)
#pragma unroll
                for (int q = 0; q < 4; q++) acc[i][j][q] = 0.f;

#pragma unroll
        for (int kc = 0; kc < 2; kc++) {
            if (!(nh == 0 && kc == 0)) __syncthreads();
#pragma unroll
            for (int i = 0; i < 4; i++) {
                int idx = t + i * 256;
                int row = idx >> 3;
                int kq  = idx & 7;
                long ga = (long)(nh * 128 + row) * K + kc * 64 + kq * 8;
                uint4 h = *(const uint4*)(bhg + ga);
                uint4 l = *(const uint4*)(blg + ga);
                uint32_t off = SW128((uint32_t)(row * 128 + kq * 16));
                *(uint4*)(smem + VW_BHI + off) = h;
                *(uint4*)(smem + VW_BLO + off) = l;
            }
            __syncthreads();
#pragma unroll
            for (int ks = 0; ks < 4; ks++) {
                uint32_t ahi[2][4], alo[2][4];
#pragma unroll
                for (int mt = 0; mt < 2; mt++) {
                    uint32_t off = SW128((uint32_t)((a_row + mt * 16) * 128 + (ks * 2 + a_atom) * 16));
                    ldsm_x4(ahi[mt], sb + VW_AHI(kc) + off);
                    ldsm_x4(alo[mt], sb + VW_ALO(kc) + off);
                }
#pragma unroll
                for (int j = 0; j < 4; j++) {
                    uint32_t offb = SW128((uint32_t)((b_row + j * 16) * 128 + (ks * 2 + b_atom) * 16));
                    uint32_t bh[4], bl[4];
                    ldsm_x4(bh, sb + VW_BHI + offb);
                    ldsm_x4(bl, sb + VW_BLO + offb);
#pragma unroll
                    for (int mt = 0; mt < 2; mt++) {
                        mma_bf16(acc[mt][2*j],   ahi[mt], bh[0], bh[1]);
                        mma_bf16(acc[mt][2*j],   alo[mt], bh[0], bh[1]);
                        mma_bf16(acc[mt][2*j],   ahi[mt], bl[0], bl[1]);
                        mma_bf16(acc[mt][2*j+1], ahi[mt], bh[2], bh[3]);
                        mma_bf16(acc[mt][2*j+1], alo[mt], bh[2], bh[3]);
                        mma_bf16(acc[mt][2*j+1], ahi[mt], bl[2], bl[3]);
                    }
                }
            }
        }
#pragma unroll
        for (int mt = 0; mt < 2; mt++) {
            int row = m0 + warp_m * 32 + mt * 16 + g;
#pragma unroll
            for (int nt = 0; nt < 8; nt++) {
                int col = nh * 128 + warp_n * 64 + nt * 8 + tg2;
                if (row < M) {
                    float2 o; o.x = acc[mt][nt][0]; o.y = acc[mt][nt][1];
                    *(float2*)(C + (long)row * N + col) = o;
                }
                if (row + 8 < M) {
                    float2 o; o.x = acc[mt][nt][2]; o.y = acc[mt][nt][3];
                    *(float2*)(C + (long)(row + 8) * N + col) = o;
                }
            }
        }
    }
}

// ============================================================
// CSR build by sender
// ============================================================
__global__ void k_count(const int* __restrict__ senders) {
    int e = blockIdx.x * blockDim.x + threadIdx.x;
    if (e < N_EDGES) atomicAdd(&g_cnt[senders[e]], 1);
}
__global__ void k_scanA() {
    __shared__ int sm[1024];
    int t = threadIdx.x;
    int i = blockIdx.x * 1024 + t;
    int v = (i < N_NODES) ? g_cnt[i] : 0;
    sm[t] = v;
    __syncthreads();
    for (int off = 1; off < 1024; off <<= 1) {
        int x = (t >= off) ? sm[t - off] : 0;
        __syncthreads();
        sm[t] += x;
        __syncthreads();
    }
    if (i < N_NODES) g_off[i] = sm[t] - v;
    if (t == 1023) g_bsum[blockIdx.x] = sm[1023];
}
__global__ void k_scanC() {
    __shared__ int pre_sh;
    if (threadIdx.x == 0) {
        int p = 0;
        for (int b = 0; b < blockIdx.x; b++) p += g_bsum[b];
        pre_sh = p;
        if (blockIdx.x == gridDim.x - 1) g_off[N_NODES] = p + g_bsum[blockIdx.x];
    }
    __syncthreads();
    int pre = pre_sh;
    int i = blockIdx.x * 1024 + threadIdx.x;
    if (i < N_NODES) {
        int o = g_off[i] + pre;
        g_off[i] = o;
        g_cur[i] = o;
    }
}
__global__ void k_fill(const int* __restrict__ senders, const int* __restrict__ receivers,
                       const float* __restrict__ dir_ij) {
    int e = blockIdx.x * blockDim.x + threadIdx.x;
    if (e < N_EDGES) {
        int p = atomicAdd(&g_cur[senders[e]], 1);
        float4 ed;
        ed.x = dir_ij[e * 3 + 0];
        ed.y = dir_ij[e * 3 + 1];
        ed.z = dir_ij[e * 3 + 2];
        ed.w = __int_as_float(e);
        g_edir[p] = ed;
        g_ercv[p] = receivers[e];
    }
}

// ============================================================
// Message gather-reduce: TWO warps per node (even/odd edge split).
// Wij evict-first; x/v gathered fp16. Partials combined via smem.
// ============================================================
__global__ void k_message(const float* __restrict__ s, const float* __restrict__ v,
                          const float* __restrict__ Wij,
                          float* __restrict__ out_s, float* __restrict__ out_v) {
    __shared__ float4 red[4][32][4];
    int gw   = (blockIdx.x * blockDim.x + threadIdx.x) >> 5;
    int node = gw >> 1;
    int half = gw & 1;
    int lane = threadIdx.x & 31;
    int pair = (threadIdx.x >> 6);
    if (node >= N_NODES) return;

    float4 ds  = f4z();
    float4 dv0 = f4z(), dv1 = f4z(), dv2 = f4z();

    int beg = g_off[node], end = g_off[node + 1];
    for (int i = beg + half; i < end; i += 2) {
        float4 ed = g_edir[i];
        int r = g_ercv[i];
        int e = __float_as_int(ed.w);
        const float4*  we = (const float4*)(Wij + (long)e * 384);
        const __half2* xr = (const __half2*)g_xh + (long)r * 192;
        const __half2* vr = (const __half2*)g_vh + (long)r * 192;

        float4 w0 = __ldcs(we + lane);
        float4 w1 = __ldcs(we + 32 + lane);
        float4 w2 = __ldcs(we + 64 + lane);
        float4 x0 = h4_to_f4(xr + lane * 2);
        float4 x1 = h4_to_f4(xr + 64 + lane * 2);
        float4 x2 = h4_to_f4(xr + 128 + lane * 2);

        ds = f4fma4(w0, x0, ds);
        float4 m1 = f4mul(w1, x1);
        float4 m2 = f4mul(w2, x2);

        float4 vj0 = h4_to_f4(vr + lane * 2);
        float4 vj1 = h4_to_f4(vr + 64 + lane * 2);
        float4 vj2 = h4_to_f4(vr + 128 + lane * 2);
        dv0 = f4fma(ed.x, m1, dv0); dv0 = f4fma4(m2, vj0, dv0);
        dv1 = f4fma(ed.y, m1, dv1); dv1 = f4fma4(m2, vj1, dv1);
        dv2 = f4fma(ed.z, m1, dv2); dv2 = f4fma4(m2, vj2, dv2);
    }

    if (half == 1) {
        red[pair][lane][0] = ds;
        red[pair][lane][1] = dv0;
        red[pair][lane][2] = dv1;
        red[pair][lane][3] = dv2;
    }
    __syncthreads();
    if (half == 0) {
        ds  = f4add(ds,  red[pair][lane][0]);
        dv0 = f4add(dv0, red[pair][lane][1]);
        dv1 = f4add(dv1, red[pair][lane][2]);
        dv2 = f4add(dv2, red[pair][lane][3]);

        float4 s4 = ((const float4*)(s + node * HDIM))[lane];
        ((float4*)(out_s + node * HDIM))[lane] = f4add(s4, f4clip(ds));

        const float4* vi = (const float4*)(v + (long)node * 384);
        float4* vo = (float4*)(out_v + (long)node * 384);
        vo[lane]      = f4add(vi[lane],      f4clip(dv0));
        vo[32 + lane] = f4add(vi[32 + lane], f4clip(dv1));
        vo[64 + lane] = f4add(vi[64 + lane], f4clip(dv2));
    }
}

// ============================================================
// Build ts (pre-split bf16 hi/lo) and dot
// ============================================================
__global__ void k_ts(const float* __restrict__ out_s) {
    long idx = (long)blockIdx.x * blockDim.x + threadIdx.x;
    if (idx >= (long)N_NODES * 32) return;
    int n  = (int)(idx >> 5);
    int c4 = (int)(idx & 31);
    const float4* vw = (const float4*)(g_vw + (long)n * 768) + c4;
    float4 vl0 = vw[0],   vr0 = vw[32];
    float4 vl1 = vw[64],  vr1 = vw[96];
    float4 vl2 = vw[128], vr2 = vw[160];
    float4 vn;
    vn.x = sqrtf(vr0.x*vr0.x + vr1.x*vr1.x + vr2.x*vr2.x + 1e-8f);
    vn.y = sqrtf(vr0.y*vr0.y + vr1.y*vr1.y + vr2.y*vr2.y + 1e-8f);
    vn.z = sqrtf(vr0.z*vr0.z + vr1.z*vr1.z + vr2.z*vr2.z + 1e-8f);
    vn.w = sqrtf(vr0.w*vr0.w + vr1.w*vr1.w + vr2.w*vr2.w + 1e-8f);

    float4 sv = ((const float4*)(out_s + (long)n * 128))[c4];
    long hb = (long)n * 128 + c4 * 2;
    uint32_t h0, l0, h1, l1;
    split2(sv.x, sv.y, h0, l0);
    split2(sv.z, sv.w, h1, l1);
    *(uint2*)(g_tshi + hb) = make_uint2(h0, h1);
    *(uint2*)(g_tslo + hb) = make_uint2(l0, l1);
    split2(vn.x, vn.y, h0, l0);
    split2(vn.z, vn.w, h1, l1);
    *(uint2*)(g_tshi + hb + 64) = make_uint2(h0, h1);
    *(uint2*)(g_tslo + hb + 64) = make_uint2(l0, l1);

    float4 dt;
    dt.x = vr0.x*vl0.x + vr1.x*vl1.x + vr2.x*vl2.x;
    dt.y = vr0.y*vl0.y + vr1.y*vl1.y + vr2.y*vl2.y;
    dt.z = vr0.z*vl0.z + vr1.z*vl1.z + vr2.z*vl2.z;
    dt.w = vr0.w*vl0.w + vr1.w*vl1.w + vr2.w*vl2.w;
    ((float4*)g_dot)[idx] = dt;
}

// ============================================================
// Final epilogue
// ============================================================
__global__ void k_final(float* __restrict__ out_s, float* __restrict__ out_v) {
    long idx = (long)blockIdx.x * blockDim.x + threadIdx.x;
    if (idx >= (long)N_NODES * 32) return;
    int n  = (int)(idx >> 5);
    int c4 = (int)(idx & 31);
    const float4* O = (const float4*)(g_o + (long)n * 384);
    float4 o0 = O[c4], o1 = O[32 + c4], o2 = O[64 + c4];
    float4 dot = ((const float4*)g_dot)[idx];
    float4 sacc = ((float4*)out_s)[idx];
    sacc.x += clip100(fmaf(o2.x, dot.x, o0.x));
    sacc.y += clip100(fmaf(o2.y, dot.y, o0.y));
    sacc.z += clip100(fmaf(o2.z, dot.z, o0.z));
    sacc.w += clip100(fmaf(o2.w, dot.w, o0.w));
    ((float4*)out_s)[idx] = sacc;
    const float4* vw = (const float4*)(g_vw + (long)n * 768);
    float4* vv = (float4*)(out_v + (long)n * 384);
#pragma unroll
    for (int d = 0; d < 3; d++) {
        float4 vl = vw[d * 64 + c4];
        float4 acc = vv[d * 32 + c4];
        acc.x += clip100(vl.x * o1.x);
        acc.y += clip100(vl.y * o1.y);
        acc.z += clip100(vl.z * o1.z);
        acc.w += clip100(vl.w * o1.w);
        vv[d * 32 + c4] = acc;
    }
}

// ============================================================
extern "C" void kernel_launch(void* const* d_in, const int* in_sizes, int n_in,
                              void* d_out, int out_size) {
    const float* s   = (const float*)d_in[0];
    const float* v   = (const float*)d_in[1];
    const float* dir = (const float*)d_in[2];
    const float* Wij = (const float*)d_in[3];
    const float* Wi1 = (const float*)d_in[4];
    const float* bi1 = (const float*)d_in[5];
    const float* Wi2 = (const float*)d_in[6];
    const float* bi2 = (const float*)d_in[7];
    const float* Wm1 = (const float*)d_in[8];
    const float* bm1 = (const float*)d_in[9];
    const float* Wm2 = (const float*)d_in[10];
    const float* bm2 = (const float*)d_in[11];
    const float* Wv  = (const float*)d_in[12];
    const int*   snd = (const int*)d_in[13];
    const int*   rcv = (const int*)d_in[14];

    float* out_s = (float*)d_out;
    float* out_v = (float*)d_out + (long)N_NODES * HDIM;

    float*    p_vw;   cudaGetSymbolAddress((void**)&p_vw,   g_vw);
    float*    p_o;    cudaGetSymbolAddress((void**)&p_o,    g_o);
    __half*   p_xh;   cudaGetSymbolAddress((void**)&p_xh,   g_xh);
    uint32_t* p_hhi;  cudaGetSymbolAddress((void**)&p_hhi,  g_hhi);
    uint32_t* p_hlo;  cudaGetSymbolAddress((void**)&p_hlo,  g_hlo);
    uint32_t* p_tshi; cudaGetSymbolAddress((void**)&p_tshi, g_tshi);
    uint32_t* p_tslo; cudaGetSymbolAddress((void**)&p_tslo, g_tslo);
    uint32_t* p_hmhi; cudaGetSymbolAddress((void**)&p_hmhi, g_hmhi);
    uint32_t* p_hmlo; cudaGetSymbolAddress((void**)&p_hmlo, g_hmlo);
    int*      p_cnt;  cudaGetSymbolAddress((void**)&p_cnt,  g_cnt);

    static cudaStream_t s2 = nullptr;
    static cudaEvent_t  e1 = nullptr, e2 = nullptr;
    if (!s2) {
        cudaStreamCreateWithFlags(&s2, cudaStreamNonBlocking);
        cudaEventCreateWithFlags(&e1, cudaEventDisableTiming);
        cudaEventCreateWithFlags(&e2, cudaEventDisableTiming);
        cudaFuncSetAttribute(k_mgemm<2,0,1>, cudaFuncAttributeMaxDynamicSharedMemorySize, MG_SMEM_TOTAL);
        cudaFuncSetAttribute(k_mgemm<1,1,2>, cudaFuncAttributeMaxDynamicSharedMemorySize, MG_SMEM_TOTAL);
        cudaFuncSetAttribute(k_mgemm<1,1,0>, cudaFuncAttributeMaxDynamicSharedMemorySize, MG_SMEM_TOTAL);
        cudaFuncSetAttribute(k_mgemm<2,1,1>, cudaFuncAttributeMaxDynamicSharedMemorySize, MG_SMEM_TOTAL);
        cudaFuncSetAttribute(k_vw, cudaFuncAttributeMaxDynamicSharedMemorySize, VW_SMEM_TOTAL);
    }

    const int TPB = 256;
    int edge_blocks = (N_EDGES + TPB - 1) / TPB;
    int msg_blocks  = (int)(((long)N_NODES * 64 + TPB - 1) / TPB);   // 2 warps/node
    int nc4_blocks = (int)(((long)N_NODES * 32 + TPB - 1) / TPB);
    int nv4_blocks = (int)(((long)N_NODES * 96 + TPB - 1) / TPB);
    const int MB  = (N_NODES + 127) / 128;        // 196
    const int MB3 = (N_NODES * 3 + 127) / 128;    // 586
    const int SCAN_BLK = (N_NODES + 1023) / 1024; // 25

    // ---- fork: v fp16 conv + CSR build on s2, concurrent with MLP GEMMs ----
    cudaEventRecord(e1, 0);
    cudaStreamWaitEvent(s2, e1, 0);
    k_convV<<<nv4_blocks, TPB, 0, s2>>>(v);
    cudaMemsetAsync(p_cnt, 0, N_NODES * sizeof(int), s2);
    k_count<<<edge_blocks, TPB, 0, s2>>>(snd);
    k_scanA<<<SCAN_BLK, 1024, 0, s2>>>();
    k_scanC<<<SCAN_BLK, 1024, 0, s2>>>();
    k_fill<<<edge_blocks, TPB, 0, s2>>>(snd, rcv, dir);
    cudaEventRecord(e2, s2);

    // ---- main stream: node MLP (x written as fp16) ----
    k_convW<<<dim3(64, 5), TPB>>>(Wi1, Wi2, Wm1, Wm2, Wv);
    k_mgemm<2,0,1><<<dim3(MB, 1), 256, MG_SMEM_TOTAL>>>(
        s, (const __nv_bfloat16*)0, (const __nv_bfloat16*)0, 0, bi1,
        (float*)0, p_hhi, p_hlo, N_NODES, 128, 128);
    k_mgemm<1,1,2><<<dim3(MB, 3), 256, MG_SMEM_TOTAL>>>(
        (const float*)0, (const __nv_bfloat16*)p_hhi, (const __nv_bfloat16*)p_hlo, 16384, bi2,
        (float*)p_xh, (uint32_t*)0, (uint32_t*)0, N_NODES, 384, 128);

    // ---- join, then message ----
    cudaStreamWaitEvent(0, e2, 0);
    k_message<<<msg_blocks, TPB>>>(s, v, Wij, out_s, out_v);

    // ---- update phase ----
    k_vw<<<MB3, 256, VW_SMEM_TOTAL>>>(out_v, p_vw);
    k_ts<<<nc4_blocks, TPB>>>(out_s);
    k_mgemm<2,1,1><<<dim3(MB, 1), 256, MG_SMEM_TOTAL>>>(
        (const float*)0, (const __nv_bfloat16*)p_tshi, (const __nv_bfloat16*)p_tslo, 65536, bm1,
        (float*)0, p_hmhi, p_hmlo, N_NODES, 128, 256);
    k_mgemm<1,1,0><<<dim3(MB, 3), 256, MG_SMEM_TOTAL>>>(
        (const float*)0, (const __nv_bfloat16*)p_hmhi, (const __nv_bfloat16*)p_hmlo, 98304, bm2,
        p_o, (uint32_t*)0, (uint32_t*)0, N_NODES, 384, 128);
    k_final<<<nc4_blocks, TPB>>>(out_s, out_v);
}

// round 16
// speedup vs baseline: 1.0719x; 1.0243x over previous
#include <cuda_runtime.h>
#include <cuda_bf16.h>
#include <cuda_fp16.h>
#include <math.h>
#include <stdint.h>

#define N_NODES 25000
#define N_EDGES 400000
#define HDIM 128

// ---- device scratch (no allocations allowed) ----
__device__ __half g_xh[N_NODES * 384];   // interaction MLP output, fp16
__device__ __half g_vh[N_NODES * 384];   // v copy, fp16 (for gathers)
__device__ __half g_vwh[N_NODES * 3 * 256];  // vw = v@Wv, fp16
__device__ float g_dot[N_NODES * 128];
__device__ float g_o [N_NODES * 384];
__device__ uint32_t g_hhi [N_NODES * 64];
__device__ uint32_t g_hlo [N_NODES * 64];
__device__ uint32_t g_tshi[N_NODES * 128];
__device__ uint32_t g_tslo[N_NODES * 128];
__device__ uint32_t g_hmhi[N_NODES * 64];
__device__ uint32_t g_hmlo[N_NODES * 64];
__device__ int    g_cnt[N_NODES];
__device__ int    g_off[N_NODES + 1];
__device__ int    g_cur[N_NODES];
__device__ float4 g_edir[N_EDGES];   // CSR-ordered {d0,d1,d2, bitcast(e)}
__device__ int    g_ercv[N_EDGES];   // CSR-ordered receiver
__device__ int    g_bsum[32];
// transposed bf16 hi/lo weights: [N][K] layout per weight
// Wi1@0 (K128,N128) Wi2@16384 (128,384) Wm1@65536 (256,128) Wm2@98304 (128,384) Wv@147456 (128,256)
__device__ __nv_bfloat16 g_whi[180224];
__device__ __nv_bfloat16 g_wlo[180224];

__device__ __forceinline__ float silu_f(float x) { return x / (1.0f + __expf(-x)); }
__device__ __forceinline__ float clip100(float x) { return fminf(fmaxf(x, -100.0f), 100.0f); }

__device__ __forceinline__ float4 f4z() { float4 r; r.x=r.y=r.z=r.w=0.f; return r; }
__device__ __forceinline__ float4 f4fma(float a, float4 b, float4 c) {
    c.x = fmaf(a, b.x, c.x); c.y = fmaf(a, b.y, c.y);
    c.z = fmaf(a, b.z, c.z); c.w = fmaf(a, b.w, c.w); return c;
}
__device__ __forceinline__ float4 f4mul(float4 a, float4 b) {
    float4 r; r.x=a.x*b.x; r.y=a.y*b.y; r.z=a.z*b.z; r.w=a.w*b.w; return r;
}
__device__ __forceinline__ float4 f4fma4(float4 a, float4 b, float4 c) {
    c.x = fmaf(a.x, b.x, c.x); c.y = fmaf(a.y, b.y, c.y);
    c.z = fmaf(a.z, b.z, c.z); c.w = fmaf(a.w, b.w, c.w); return c;
}
__device__ __forceinline__ float4 f4add(float4 a, float4 b) {
    float4 r; r.x=a.x+b.x; r.y=a.y+b.y; r.z=a.z+b.z; r.w=a.w+b.w; return r;
}
__device__ __forceinline__ float4 f4clip(float4 a) {
    float4 r; r.x=clip100(a.x); r.y=clip100(a.y); r.z=clip100(a.z); r.w=clip100(a.w); return r;
}
// load 4 consecutive halfs (8B) -> float4
__device__ __forceinline__ float4 h4_to_f4(const __half2* p) {
    uint2 u = *(const uint2*)p;
    __half2 a = *(__half2*)&u.x;
    __half2 b = *(__half2*)&u.y;
    float2 fa = __half22float2(a);
    float2 fb = __half22float2(b);
    float4 r; r.x = fa.x; r.y = fa.y; r.z = fb.x; r.w = fb.y;
    return r;
}

__device__ __forceinline__ uint32_t smem_u32(const void* p) {
    uint32_t a;
    asm("{ .reg .u64 tmp; cvta.to.shared.u64 tmp, %1; cvt.u32.u64 %0, tmp; }"
        : "=r"(a) : "l"(p));
    return a;
}
__device__ __forceinline__ uint32_t cvt_bf2(float a, float b) {
    uint32_t r;
    asm("cvt.rn.bf16x2.f32 %0, %1, %2;" : "=r"(r) : "f"(b), "f"(a));
    return r;
}
__device__ __forceinline__ void split2(float a, float b, uint32_t& h, uint32_t& l) {
    h = cvt_bf2(a, b);
    float r0 = a - __uint_as_float(h << 16);
    float r1 = b - __uint_as_float(h & 0xFFFF0000u);
    l = cvt_bf2(r0, r1);
}
__device__ __forceinline__ void ldsm_x4(uint32_t* r, uint32_t addr) {
    asm volatile("ldmatrix.sync.aligned.m8n8.x4.shared.b16 {%0,%1,%2,%3}, [%4];"
                 : "=r"(r[0]), "=r"(r[1]), "=r"(r[2]), "=r"(r[3]) : "r"(addr));
}
__device__ __forceinline__ void mma_bf16(float* d, const uint32_t* a, uint32_t b0, uint32_t b1) {
    asm volatile("mma.sync.aligned.m16n8k16.row.col.f32.bf16.bf16.f32 "
        "{%0,%1,%2,%3}, {%4,%5,%6,%7}, {%8,%9}, {%0,%1,%2,%3};"
        : "+f"(d[0]), "+f"(d[1]), "+f"(d[2]), "+f"(d[3])
        : "r"(a[0]), "r"(a[1]), "r"(a[2]), "r"(a[3]), "r"(b0), "r"(b1));
}
#define SW128(o) ((o) ^ (((o) >> 3) & 0x70))

// ============================================================
// Weight pre-convert: W[K,N] fp32 -> Wt[N][K] bf16 hi/lo
// ============================================================
__global__ void k_convW(const float* __restrict__ W0, const float* __restrict__ W1,
                        const float* __restrict__ W2, const float* __restrict__ W3,
                        const float* __restrict__ W4) {
    const float* srcs[5] = {W0, W1, W2, W3, W4};
    const int Ks[5]   = {128, 128, 256, 128, 128};
    const int Ns[5]   = {128, 384, 128, 384, 256};
    const int offs[5] = {0, 16384, 65536, 98304, 147456};
    int w = blockIdx.y;
    const float* W = srcs[w];
    int K = Ks[w], N = Ns[w], off = offs[w];
    int total = K * N;
    for (int idx = blockIdx.x * blockDim.x + threadIdx.x; idx < total;
         idx += gridDim.x * blockDim.x) {
        int n = idx / K, k = idx - n * K;
        float v = W[k * N + n];
        __nv_bfloat16 h = __float2bfloat16(v);
        float r = v - __bfloat162float(h);
        g_whi[off + idx] = h;
        g_wlo[off + idx] = __float2bfloat16(r);
    }
}

// v fp32 -> fp16 copy (for message gathers)
__global__ void k_convV(const float* __restrict__ v) {
    long i = (long)blockIdx.x * blockDim.x + threadIdx.x;   // over N*96 float4 groups
    if (i >= (long)N_NODES * 96) return;
    float4 a = ((const float4*)v)[i];
    __half2 h0 = __floats2half2_rn(a.x, a.y);
    __half2 h1 = __floats2half2_rn(a.z, a.w);
    uint2 u;
    u.x = *(uint32_t*)&h0;
    u.y = *(uint32_t*)&h1;
    *(uint2*)(g_vh + i * 4) = u;
}

// ============================================================
// General split-bf16 mma.sync GEMM (R8-proven).
// OSPLIT: 0 = fp32 C, 1 = packed bf16 hi/lo (chi/clo), 2 = fp16 (C cast to __half*)
// ============================================================
#define MG_OFF_AHI   0
#define MG_OFF_ALO   16384
#define MG_OFF_BHI   32768
#define MG_OFF_BLO   49152
#define MG_SMEM_TOTAL 65536

template<int EPI, int ASPLIT, int OSPLIT>
__global__ __launch_bounds__(256, 2)
void k_mgemm(const float* __restrict__ A,
             const __nv_bfloat16* __restrict__ ahi_g, const __nv_bfloat16* __restrict__ alo_g,
             int woff, const float* __restrict__ bias,
             float* __restrict__ C, uint32_t* __restrict__ chi, uint32_t* __restrict__ clo,
             int M, int N, int K)
{
    extern __shared__ char smem[];
    const uint32_t sb = smem_u32(smem);

    const int t = threadIdx.x;
    const int lane = t & 31;
    const int wid = t >> 5;
    const int warp_m = wid & 3;
    const int warp_n = wid >> 2;
    const int m0 = blockIdx.x * 128;
    const int n0 = blockIdx.y * 128;

    const __nv_bfloat16* bhg = g_whi + woff;
    const __nv_bfloat16* blg = g_wlo + woff;

    float acc[2][8][4];
#pragma unroll
    for (int i = 0; i < 2; i++)
#pragma unroll
        for (int j = 0; j < 8; j++)
#pragma unroll
            for (int q = 0; q < 4; q++) acc[i][j][q] = 0.f;

    const int a_row  = warp_m * 32 + (lane & 15);
    const int a_atom = lane >> 4;
    const int b_row  = warp_n * 64 + (lane & 7) + ((lane & 16) ? 8 : 0);
    const int b_atom = (lane >> 3) & 1;

    const int nchunk = K >> 6;
    for (int c = 0; c < nchunk; c++) {
        const int k0 = c << 6;
        if (ASPLIT) {
#pragma unroll
            for (int i = 0; i < 4; i++) {
                int idx = t + i * 256;
                int row = idx >> 3;
                int kq  = idx & 7;
                uint4 h = make_uint4(0,0,0,0), l = make_uint4(0,0,0,0);
                if (m0 + row < M) {
                    long ga = (long)(m0 + row) * K + k0 + kq * 8;
                    h = *(const uint4*)(ahi_g + ga);
                    l = *(const uint4*)(alo_g + ga);
                }
                uint32_t off = SW128((uint32_t)(row * 128 + kq * 16));
                *(uint4*)(smem + MG_OFF_AHI + off) = h;
                *(uint4*)(smem + MG_OFF_ALO + off) = l;
            }
        } else {
#pragma unroll
            for (int i = 0; i < 8; i++) {
                int idx = t + i * 256;
                int row = idx >> 4;
                int kq  = idx & 15;
                float4 a = f4z();
                if (m0 + row < M) a = *(const float4*)(A + (long)(m0 + row) * K + k0 + kq * 4);
                uint32_t h0, l0, h1, l1;
                split2(a.x, a.y, h0, l0);
                split2(a.z, a.w, h1, l1);
                uint32_t off = SW128((uint32_t)(row * 128 + kq * 8));
                *(uint2*)(smem + MG_OFF_AHI + off) = make_uint2(h0, h1);
                *(uint2*)(smem + MG_OFF_ALO + off) = make_uint2(l0, l1);
            }
        }
#pragma unroll
        for (int i = 0; i < 4; i++) {
            int idx = t + i * 256;
            int row = idx >> 3;
            int kq  = idx & 7;
            long ga = (long)(n0 + row) * K + k0 + kq * 8;
            uint4 h = *(const uint4*)(bhg + ga);
            uint4 l = *(const uint4*)(blg + ga);
            uint32_t off = SW128((uint32_t)(row * 128 + kq * 16));
            *(uint4*)(smem + MG_OFF_BHI + off) = h;
            *(uint4*)(smem + MG_OFF_BLO + off) = l;
        }
        __syncthreads();
#pragma unroll
        for (int ks = 0; ks < 4; ks++) {
            uint32_t ahi[2][4], alo[2][4];
#pragma unroll
            for (int mt = 0; mt < 2; mt++) {
                uint32_t off = SW128((uint32_t)((a_row + mt * 16) * 128 + (ks * 2 + a_atom) * 16));
                ldsm_x4(ahi[mt], sb + MG_OFF_AHI + off);
                ldsm_x4(alo[mt], sb + MG_OFF_ALO + off);
            }
#pragma unroll
            for (int j = 0; j < 4; j++) {
                uint32_t offb = SW128((uint32_t)((b_row + j * 16) * 128 + (ks * 2 + b_atom) * 16));
                uint32_t bh[4], bl[4];
                ldsm_x4(bh, sb + MG_OFF_BHI + offb);
                ldsm_x4(bl, sb + MG_OFF_BLO + offb);
#pragma unroll
                for (int mt = 0; mt < 2; mt++) {
                    mma_bf16(acc[mt][2*j],   ahi[mt], bh[0], bh[1]);
                    mma_bf16(acc[mt][2*j],   alo[mt], bh[0], bh[1]);
                    mma_bf16(acc[mt][2*j],   ahi[mt], bl[0], bl[1]);
                    mma_bf16(acc[mt][2*j+1], ahi[mt], bh[2], bh[3]);
                    mma_bf16(acc[mt][2*j+1], alo[mt], bh[2], bh[3]);
                    mma_bf16(acc[mt][2*j+1], ahi[mt], bl[2], bl[3]);
                }
            }
        }
        __syncthreads();
    }

    const int g   = lane >> 2;
    const int tg2 = (lane & 3) * 2;
#pragma unroll
    for (int mt = 0; mt < 2; mt++) {
        int row = m0 + warp_m * 32 + mt * 16 + g;
#pragma unroll
        for (int nt = 0; nt < 8; nt++) {
            int col = n0 + warp_n * 64 + nt * 8 + tg2;
            float d0 = acc[mt][nt][0], d1 = acc[mt][nt][1];
            float d2 = acc[mt][nt][2], d3 = acc[mt][nt][3];
            if (EPI > 0) {
                float b0 = bias[col], b1 = bias[col + 1];
                d0 += b0; d1 += b1; d2 += b0; d3 += b1;
            }
            if (EPI == 2) {
                d0 = silu_f(d0); d1 = silu_f(d1); d2 = silu_f(d2); d3 = silu_f(d3);
            }
            if (OSPLIT == 1) {
                if (row < M) {
                    uint32_t h, l; split2(d0, d1, h, l);
                    long hx = ((long)row * N + col) >> 1;
                    chi[hx] = h; clo[hx] = l;
                }
                if (row + 8 < M) {
                    uint32_t h, l; split2(d2, d3, h, l);
                    long hx = ((long)(row + 8) * N + col) >> 1;
                    chi[hx] = h; clo[hx] = l;
                }
            } else if (OSPLIT == 2) {
                __half* Ch = (__half*)C;
                if (row < M) {
                    __half2 o = __floats2half2_rn(d0, d1);
                    *(__half2*)(Ch + (long)row * N + col) = o;
                }
                if (row + 8 < M) {
                    __half2 o = __floats2half2_rn(d2, d3);
                    *(__half2*)(Ch + (long)(row + 8) * N + col) = o;
                }
            } else {
                if (row < M) {
                    float2 o; o.x = d0; o.y = d1;
                    *(float2*)(C + (long)row * N + col) = o;
                }
                if (row + 8 < M) {
                    float2 o; o.x = d2; o.y = d3;
                    *(float2*)(C + (long)(row + 8) * N + col) = o;
                }
            }
        }
    }
}

// ============================================================
// vw GEMM: g_vwh[75000,256] (fp16) = out_v[75000,128] @ Wv
// ============================================================
#define VW_AHI(kc) ((kc) * 16384)
#define VW_ALO(kc) (32768 + (kc) * 16384)
#define VW_BHI 65536
#define VW_BLO 81920
#define VW_SMEM_TOTAL 98304

__global__ __launch_bounds__(256, 2)
void k_vw(const float* __restrict__ A, __half* __restrict__ C)
{
    const int M = N_NODES * 3, K = 128, N = 256;
    extern __shared__ char smem[];
    const uint32_t sb = smem_u32(smem);

    const int t = threadIdx.x;
    const int lane = t & 31;
    const int wid = t >> 5;
    const int warp_m = wid & 3;
    const int warp_n = wid >> 2;
    const int m0 = blockIdx.x * 128;

    const __nv_bfloat16* bhg = g_whi + 147456;
    const __nv_bfloat16* blg = g_wlo + 147456;

    const int a_row  = warp_m * 32 + (lane & 15);
    const int a_atom = lane >> 4;
    const int b_row  = warp_n * 64 + (lane & 7) + ((lane & 16) ? 8 : 0);
    const int b_atom = (lane >> 3) & 1;

#pragma unroll
    for (int i = 0; i < 16; i++) {
        int idx = t + i * 256;
        int row = idx >> 5;
        int kq4 = idx & 31;
        int kc  = kq4 >> 4;
        int kq  = kq4 & 15;
        float4 a = f4z();
        if (m0 + row < M) a = *(const float4*)(A + (long)(m0 + row) * K + kq4 * 4);
        uint32_t h0, l0, h1, l1;
        split2(a.x, a.y, h0, l0);
        split2(a.z, a.w, h1, l1);
        uint32_t off = SW128((uint32_t)(row * 128 + kq * 8));
        *(uint2*)(smem + VW_AHI(kc) + off) = make_uint2(h0, h1);
        *(uint2*)(smem + VW_ALO(kc) + off) = make_uint2(l0, l1);
    }
    __syncthreads();

    const int g   = lane >> 2;
    const int tg2 = (lane & 3) * 2;

#pragma unroll
    for (int nh = 0; nh < 2; nh++) {
        float acc[2][8][4];
#pragma unroll
        for (int i = 0; i < 2; i++)
#pragma unroll
            for (int j = 0; j < 8; j++)
#pragma unroll
                for (int q = 0; q < 4; q++) acc[i][j][q] = 0.f;

#pragma unroll
        for (int kc = 0; kc < 2; kc++) {
            if (!(nh == 0 && kc == 0)) __syncthreads();
#pragma unroll
            for (int i = 0; i < 4; i++) {
                int idx = t + i * 256;
                int row = idx >> 3;
                int kq  = idx & 7;
                long ga = (long)(nh * 128 + row) * K + kc * 64 + kq * 8;
                uint4 h = *(const uint4*)(bhg + ga);
                uint4 l = *(const uint4*)(blg + ga);
                uint32_t off = SW128((uint32_t)(row * 128 + kq * 16));
                *(uint4*)(smem + VW_BHI + off) = h;
                *(uint4*)(smem + VW_BLO + off) = l;
            }
            __syncthreads();
#pragma unroll
            for (int ks = 0; ks < 4; ks++) {
                uint32_t ahi[2][4], alo[2][4];
#pragma unroll
                for (int mt = 0; mt < 2; mt++) {
                    uint32_t off = SW128((uint32_t)((a_row + mt * 16) * 128 + (ks * 2 + a_atom) * 16));
                    ldsm_x4(ahi[mt], sb + VW_AHI(kc) + off);
                    ldsm_x4(alo[mt], sb + VW_ALO(kc) + off);
                }
#pragma unroll
                for (int j = 0; j < 4; j++) {
                    uint32_t offb = SW128((uint32_t)((b_row + j * 16) * 128 + (ks * 2 + b_atom) * 16));
                    uint32_t bh[4], bl[4];
                    ldsm_x4(bh, sb + VW_BHI + offb);
                    ldsm_x4(bl, sb + VW_BLO + offb);
#pragma unroll
                    for (int mt = 0; mt < 2; mt++) {
                        mma_bf16(acc[mt][2*j],   ahi[mt], bh[0], bh[1]);
                        mma_bf16(acc[mt][2*j],   alo[mt], bh[0], bh[1]);
                        mma_bf16(acc[mt][2*j],   ahi[mt], bl[0], bl[1]);
                        mma_bf16(acc[mt][2*j+1], ahi[mt], bh[2], bh[3]);
                        mma_bf16(acc[mt][2*j+1], alo[mt], bh[2], bh[3]);
                        mma_bf16(acc[mt][2*j+1], ahi[mt], bl[2], bl[3]);
                    }
                }
            }
        }
#pragma unroll
        for (int mt = 0; mt < 2; mt++) {
            int row = m0 + warp_m * 32 + mt * 16 + g;
#pragma unroll
            for (int nt = 0; nt < 8; nt++) {
                int col = nh * 128 + warp_n * 64 + nt * 8 + tg2;
                if (row < M) {
                    __half2 o = __floats2half2_rn(acc[mt][nt][0], acc[mt][nt][1]);
                    *(__half2*)(C + (long)row * N + col) = o;
                }
                if (row + 8 < M) {
                    __half2 o = __floats2half2_rn(acc[mt][nt][2], acc[mt][nt][3]);
                    *(__half2*)(C + (long)(row + 8) * N + col) = o;
                }
            }
        }
    }
}

// ============================================================
// CSR build by sender
// ============================================================
__global__ void k_count(const int* __restrict__ senders) {
    int e = blockIdx.x * blockDim.x + threadIdx.x;
    if (e < N_EDGES) atomicAdd(&g_cnt[senders[e]], 1);
}
__global__ void k_scanA() {
    __shared__ int sm[1024];
    int t = threadIdx.x;
    int i = blockIdx.x * 1024 + t;
    int v = (i < N_NODES) ? g_cnt[i] : 0;
    sm[t] = v;
    __syncthreads();
    for (int off = 1; off < 1024; off <<= 1) {
        int x = (t >= off) ? sm[t - off] : 0;
        __syncthreads();
        sm[t] += x;
        __syncthreads();
    }
    if (i < N_NODES) g_off[i] = sm[t] - v;
    if (t == 1023) g_bsum[blockIdx.x] = sm[1023];
}
__global__ void k_scanC() {
    __shared__ int pre_sh;
    if (threadIdx.x == 0) {
        int p = 0;
        for (int b = 0; b < blockIdx.x; b++) p += g_bsum[b];
        pre_sh = p;
        if (blockIdx.x == gridDim.x - 1) g_off[N_NODES] = p + g_bsum[blockIdx.x];
    }
    __syncthreads();
    int pre = pre_sh;
    int i = blockIdx.x * 1024 + threadIdx.x;
    if (i < N_NODES) {
        int o = g_off[i] + pre;
        g_off[i] = o;
        g_cur[i] = o;
    }
}
__global__ void k_fill(const int* __restrict__ senders, const int* __restrict__ receivers,
                       const float* __restrict__ dir_ij) {
    int e = blockIdx.x * blockDim.x + threadIdx.x;
    if (e < N_EDGES) {
        int p = atomicAdd(&g_cur[senders[e]], 1);
        float4 ed;
        ed.x = dir_ij[e * 3 + 0];
        ed.y = dir_ij[e * 3 + 1];
        ed.z = dir_ij[e * 3 + 2];
        ed.w = __int_as_float(e);
        g_edir[p] = ed;
        g_ercv[p] = receivers[e];
    }
}

// ============================================================
// Message gather-reduce: TWO warps per node (even/odd edge split).
// Wij evict-first; x/v gathered fp16. Partials combined via smem.
// ============================================================
__global__ void k_message(const float* __restrict__ s, const float* __restrict__ v,
                          const float* __restrict__ Wij,
                          float* __restrict__ out_s, float* __restrict__ out_v) {
    __shared__ float4 red[4][32][4];
    int gw   = (blockIdx.x * blockDim.x + threadIdx.x) >> 5;
    int node = gw >> 1;
    int half = gw & 1;
    int lane = threadIdx.x & 31;
    int pair = (threadIdx.x >> 6);
    if (node >= N_NODES) return;

    float4 ds  = f4z();
    float4 dv0 = f4z(), dv1 = f4z(), dv2 = f4z();

    int beg = g_off[node], end = g_off[node + 1];
    for (int i = beg + half; i < end; i += 2) {
        float4 ed = g_edir[i];
        int r = g_ercv[i];
        int e = __float_as_int(ed.w);
        const float4*  we = (const float4*)(Wij + (long)e * 384);
        const __half2* xr = (const __half2*)g_xh + (long)r * 192;
        const __half2* vr = (const __half2*)g_vh + (long)r * 192;

        float4 w0 = __ldcs(we + lane);
        float4 w1 = __ldcs(we + 32 + lane);
        float4 w2 = __ldcs(we + 64 + lane);
        float4 x0 = h4_to_f4(xr + lane * 2);
        float4 x1 = h4_to_f4(xr + 64 + lane * 2);
        float4 x2 = h4_to_f4(xr + 128 + lane * 2);

        ds = f4fma4(w0, x0, ds);
        float4 m1 = f4mul(w1, x1);
        float4 m2 = f4mul(w2, x2);

        float4 vj0 = h4_to_f4(vr + lane * 2);
        float4 vj1 = h4_to_f4(vr + 64 + lane * 2);
        float4 vj2 = h4_to_f4(vr + 128 + lane * 2);
        dv0 = f4fma(ed.x, m1, dv0); dv0 = f4fma4(m2, vj0, dv0);
        dv1 = f4fma(ed.y, m1, dv1); dv1 = f4fma4(m2, vj1, dv1);
        dv2 = f4fma(ed.z, m1, dv2); dv2 = f4fma4(m2, vj2, dv2);
    }

    if (half == 1) {
        red[pair][lane][0] = ds;
        red[pair][lane][1] = dv0;
        red[pair][lane][2] = dv1;
        red[pair][lane][3] = dv2;
    }
    __syncthreads();
    if (half == 0) {
        ds  = f4add(ds,  red[pair][lane][0]);
        dv0 = f4add(dv0, red[pair][lane][1]);
        dv1 = f4add(dv1, red[pair][lane][2]);
        dv2 = f4add(dv2, red[pair][lane][3]);

        float4 s4 = ((const float4*)(s + node * HDIM))[lane];
        ((float4*)(out_s + node * HDIM))[lane] = f4add(s4, f4clip(ds));

        const float4* vi = (const float4*)(v + (long)node * 384);
        float4* vo = (float4*)(out_v + (long)node * 384);
        vo[lane]      = f4add(vi[lane],      f4clip(dv0));
        vo[32 + lane] = f4add(vi[32 + lane], f4clip(dv1));
        vo[64 + lane] = f4add(vi[64 + lane], f4clip(dv2));
    }
}

// ============================================================
// Build ts (pre-split bf16 hi/lo) and dot  (reads g_vwh fp16)
// ============================================================
__global__ void k_ts(const float* __restrict__ out_s) {
    long idx = (long)blockIdx.x * blockDim.x + threadIdx.x;
    if (idx >= (long)N_NODES * 32) return;
    int n  = (int)(idx >> 5);
    int c4 = (int)(idx & 31);
    const __half2* vw = (const __half2*)(g_vwh + (long)n * 768);
    float4 vl0 = h4_to_f4(vw + c4 * 2),       vr0 = h4_to_f4(vw + 64 + c4 * 2);
    float4 vl1 = h4_to_f4(vw + 128 + c4 * 2), vr1 = h4_to_f4(vw + 192 + c4 * 2);
    float4 vl2 = h4_to_f4(vw + 256 + c4 * 2), vr2 = h4_to_f4(vw + 320 + c4 * 2);
    float4 vn;
    vn.x = sqrtf(vr0.x*vr0.x + vr1.x*vr1.x + vr2.x*vr2.x + 1e-8f);
    vn.y = sqrtf(vr0.y*vr0.y + vr1.y*vr1.y + vr2.y*vr2.y + 1e-8f);
    vn.z = sqrtf(vr0.z*vr0.z + vr1.z*vr1.z + vr2.z*vr2.z + 1e-8f);
    vn.w = sqrtf(vr0.w*vr0.w + vr1.w*vr1.w + vr2.w*vr2.w + 1e-8f);

    float4 sv = ((const float4*)(out_s + (long)n * 128))[c4];
    long hb = (long)n * 128 + c4 * 2;
    uint32_t h0, l0, h1, l1;
    split2(sv.x, sv.y, h0, l0);
    split2(sv.z, sv.w, h1, l1);
    *(uint2*)(g_tshi + hb) = make_uint2(h0, h1);
    *(uint2*)(g_tslo + hb) = make_uint2(l0, l1);
    split2(vn.x, vn.y, h0, l0);
    split2(vn.z, vn.w, h1, l1);
    *(uint2*)(g_tshi + hb + 64) = make_uint2(h0, h1);
    *(uint2*)(g_tslo + hb + 64) = make_uint2(l0, l1);

    float4 dt;
    dt.x = vr0.x*vl0.x + vr1.x*vl1.x + vr2.x*vl2.x;
    dt.y = vr0.y*vl0.y + vr1.y*vl1.y + vr2.y*vl2.y;
    dt.z = vr0.z*vl0.z + vr1.z*vl1.z + vr2.z*vl2.z;
    dt.w = vr0.w*vl0.w + vr1.w*vl1.w + vr2.w*vl2.w;
    ((float4*)g_dot)[idx] = dt;
}

// ============================================================
// Final epilogue  (reads g_vwh fp16)
// ============================================================
__global__ void k_final(float* __restrict__ out_s, float* __restrict__ out_v) {
    long idx = (long)blockIdx.x * blockDim.x + threadIdx.x;
    if (idx >= (long)N_NODES * 32) return;
    int n  = (int)(idx >> 5);
    int c4 = (int)(idx & 31);
    const float4* O = (const float4*)(g_o + (long)n * 384);
    float4 o0 = O[c4], o1 = O[32 + c4], o2 = O[64 + c4];
    float4 dot = ((const float4*)g_dot)[idx];
    float4 sacc = ((float4*)out_s)[idx];
    sacc.x += clip100(fmaf(o2.x, dot.x, o0.x));
    sacc.y += clip100(fmaf(o2.y, dot.y, o0.y));
    sacc.z += clip100(fmaf(o2.z, dot.z, o0.z));
    sacc.w += clip100(fmaf(o2.w, dot.w, o0.w));
    ((float4*)out_s)[idx] = sacc;
    const __half2* vw = (const __half2*)(g_vwh + (long)n * 768);
    float4* vv = (float4*)(out_v + (long)n * 384);
#pragma unroll
    for (int d = 0; d < 3; d++) {
        float4 vl = h4_to_f4(vw + d * 128 + c4 * 2);
        float4 acc = vv[d * 32 + c4];
        acc.x += clip100(vl.x * o1.x);
        acc.y += clip100(vl.y * o1.y);
        acc.z += clip100(vl.z * o1.z);
        acc.w += clip100(vl.w * o1.w);
        vv[d * 32 + c4] = acc;
    }
}

// ============================================================
extern "C" void kernel_launch(void* const* d_in, const int* in_sizes, int n_in,
                              void* d_out, int out_size) {
    const float* s   = (const float*)d_in[0];
    const float* v   = (const float*)d_in[1];
    const float* dir = (const float*)d_in[2];
    const float* Wij = (const float*)d_in[3];
    const float* Wi1 = (const float*)d_in[4];
    const float* bi1 = (const float*)d_in[5];
    const float* Wi2 = (const float*)d_in[6];
    const float* bi2 = (const float*)d_in[7];
    const float* Wm1 = (const float*)d_in[8];
    const float* bm1 = (const float*)d_in[9];
    const float* Wm2 = (const float*)d_in[10];
    const float* bm2 = (const float*)d_in[11];
    const float* Wv  = (const float*)d_in[12];
    const int*   snd = (const int*)d_in[13];
    const int*   rcv = (const int*)d_in[14];

    float* out_s = (float*)d_out;
    float* out_v = (float*)d_out + (long)N_NODES * HDIM;

    float*    p_o;    cudaGetSymbolAddress((void**)&p_o,    g_o);
    __half*   p_xh;   cudaGetSymbolAddress((void**)&p_xh,   g_xh);
    __half*   p_vwh;  cudaGetSymbolAddress((void**)&p_vwh,  g_vwh);
    uint32_t* p_hhi;  cudaGetSymbolAddress((void**)&p_hhi,  g_hhi);
    uint32_t* p_hlo;  cudaGetSymbolAddress((void**)&p_hlo,  g_hlo);
    uint32_t* p_tshi; cudaGetSymbolAddress((void**)&p_tshi, g_tshi);
    uint32_t* p_tslo; cudaGetSymbolAddress((void**)&p_tslo, g_tslo);
    uint32_t* p_hmhi; cudaGetSymbolAddress((void**)&p_hmhi, g_hmhi);
    uint32_t* p_hmlo; cudaGetSymbolAddress((void**)&p_hmlo, g_hmlo);
    int*      p_cnt;  cudaGetSymbolAddress((void**)&p_cnt,  g_cnt);

    static cudaStream_t s2 = nullptr;
    static cudaEvent_t  e1 = nullptr, e2 = nullptr;
    if (!s2) {
        cudaStreamCreateWithFlags(&s2, cudaStreamNonBlocking);
        cudaEventCreateWithFlags(&e1, cudaEventDisableTiming);
        cudaEventCreateWithFlags(&e2, cudaEventDisableTiming);
        cudaFuncSetAttribute(k_mgemm<2,0,1>, cudaFuncAttributeMaxDynamicSharedMemorySize, MG_SMEM_TOTAL);
        cudaFuncSetAttribute(k_mgemm<1,1,2>, cudaFuncAttributeMaxDynamicSharedMemorySize, MG_SMEM_TOTAL);
        cudaFuncSetAttribute(k_mgemm<1,1,0>, cudaFuncAttributeMaxDynamicSharedMemorySize, MG_SMEM_TOTAL);
        cudaFuncSetAttribute(k_mgemm<2,1,1>, cudaFuncAttributeMaxDynamicSharedMemorySize, MG_SMEM_TOTAL);
        cudaFuncSetAttribute(k_vw, cudaFuncAttributeMaxDynamicSharedMemorySize, VW_SMEM_TOTAL);
    }

    const int TPB = 256;
    int edge_blocks = (N_EDGES + TPB - 1) / TPB;
    int msg_blocks  = (int)(((long)N_NODES * 64 + TPB - 1) / TPB);   // 2 warps/node
    int nc4_blocks = (int)(((long)N_NODES * 32 + TPB - 1) / TPB);
    int nv4_blocks = (int)(((long)N_NODES * 96 + TPB - 1) / TPB);
    const int MB  = (N_NODES + 127) / 128;        // 196
    const int MB3 = (N_NODES * 3 + 127) / 128;    // 586
    const int SCAN_BLK = (N_NODES + 1023) / 1024; // 25

    // ---- fork: v fp16 conv + CSR build on s2, concurrent with MLP GEMMs ----
    cudaEventRecord(e1, 0);
    cudaStreamWaitEvent(s2, e1, 0);
    k_convV<<<nv4_blocks, TPB, 0, s2>>>(v);
    cudaMemsetAsync(p_cnt, 0, N_NODES * sizeof(int), s2);
    k_count<<<edge_blocks, TPB, 0, s2>>>(snd);
    k_scanA<<<SCAN_BLK, 1024, 0, s2>>>();
    k_scanC<<<SCAN_BLK, 1024, 0, s2>>>();
    k_fill<<<edge_blocks, TPB, 0, s2>>>(snd, rcv, dir);
    cudaEventRecord(e2, s2);

    // ---- main stream: node MLP (x written as fp16) ----
    k_convW<<<dim3(64, 5), TPB>>>(Wi1, Wi2, Wm1, Wm2, Wv);
    k_mgemm<2,0,1><<<dim3(MB, 1), 256, MG_SMEM_TOTAL>>>(
        s, (const __nv_bfloat16*)0, (const __nv_bfloat16*)0, 0, bi1,
        (float*)0, p_hhi, p_hlo, N_NODES, 128, 128);
    k_mgemm<1,1,2><<<dim3(MB, 3), 256, MG_SMEM_TOTAL>>>(
        (const float*)0, (const __nv_bfloat16*)p_hhi, (const __nv_bfloat16*)p_hlo, 16384, bi2,
        (float*)p_xh, (uint32_t*)0, (uint32_t*)0, N_NODES, 384, 128);

    // ---- join, then message ----
    cudaStreamWaitEvent(0, e2, 0);
    k_message<<<msg_blocks, TPB>>>(s, v, Wij, out_s, out_v);

    // ---- update phase ----
    k_vw<<<MB3, 256, VW_SMEM_TOTAL>>>(out_v, p_vwh);
    k_ts<<<nc4_blocks, TPB>>>(out_s);
    k_mgemm<2,1,1><<<dim3(MB, 1), 256, MG_SMEM_TOTAL>>>(
        (const float*)0, (const __nv_bfloat16*)p_tshi, (const __nv_bfloat16*)p_tslo, 65536, bm1,
        (float*)0, p_hmhi, p_hmlo, N_NODES, 128, 256);
    k_mgemm<1,1,0><<<dim3(MB, 3), 256, MG_SMEM_TOTAL>>>(
        (const float*)0, (const __nv_bfloat16*)p_hmhi, (const __nv_bfloat16*)p_hmlo, 98304, bm2,
        p_o, (uint32_t*)0, (uint32_t*)0, N_NODES, 384, 128);
    k_final<<<nc4_blocks, TPB>>>(out_s, out_v);
}

// round 17
// speedup vs baseline: 1.0846x; 1.0118x over previous
#include <cuda_runtime.h>
#include <cuda_bf16.h>
#include <cuda_fp16.h>
#include <math.h>
#include <stdint.h>

#define N_NODES 25000
#define N_EDGES 400000
#define HDIM 128

// ---- device scratch (no allocations allowed) ----
__device__ __half g_xh[N_NODES * 384];   // interaction MLP output, fp16
__device__ __half g_vh[N_NODES * 384];   // v copy, fp16 (for gathers)
__device__ __half g_vwh[N_NODES * 3 * 256];  // vw = v@Wv, fp16
__device__ __half g_oh[N_NODES * 384];   // mixing MLP output, fp16
__device__ __half g_doth[N_NODES * 128]; // dot, fp16
__device__ uint32_t g_hhi [N_NODES * 64];
__device__ uint32_t g_hlo [N_NODES * 64];
__device__ uint32_t g_tshi[N_NODES * 128];
__device__ uint32_t g_tslo[N_NODES * 128];
__device__ uint32_t g_hmhi[N_NODES * 64];
__device__ uint32_t g_hmlo[N_NODES * 64];
__device__ int    g_cnt[N_NODES];
__device__ int    g_off[N_NODES + 1];
__device__ int    g_cur[N_NODES];
__device__ float4 g_edir[N_EDGES];   // CSR-ordered {d0,d1,d2, bitcast(e)}
__device__ int    g_ercv[N_EDGES];   // CSR-ordered receiver
__device__ int    g_bsum[32];
// transposed bf16 hi/lo weights: [N][K] layout per weight
// Wi1@0 (K128,N128) Wi2@16384 (128,384) Wm1@65536 (256,128) Wm2@98304 (128,384) Wv@147456 (128,256)
__device__ __nv_bfloat16 g_whi[180224];
__device__ __nv_bfloat16 g_wlo[180224];

__device__ __forceinline__ float silu_f(float x) { return x / (1.0f + __expf(-x)); }
__device__ __forceinline__ float clip100(float x) { return fminf(fmaxf(x, -100.0f), 100.0f); }

__device__ __forceinline__ float4 f4z() { float4 r; r.x=r.y=r.z=r.w=0.f; return r; }
__device__ __forceinline__ float4 f4fma(float a, float4 b, float4 c) {
    c.x = fmaf(a, b.x, c.x); c.y = fmaf(a, b.y, c.y);
    c.z = fmaf(a, b.z, c.z); c.w = fmaf(a, b.w, c.w); return c;
}
__device__ __forceinline__ float4 f4mul(float4 a, float4 b) {
    float4 r; r.x=a.x*b.x; r.y=a.y*b.y; r.z=a.z*b.z; r.w=a.w*b.w; return r;
}
__device__ __forceinline__ float4 f4fma4(float4 a, float4 b, float4 c) {
    c.x = fmaf(a.x, b.x, c.x); c.y = fmaf(a.y, b.y, c.y);
    c.z = fmaf(a.z, b.z, c.z); c.w = fmaf(a.w, b.w, c.w); return c;
}
__device__ __forceinline__ float4 f4add(float4 a, float4 b) {
    float4 r; r.x=a.x+b.x; r.y=a.y+b.y; r.z=a.z+b.z; r.w=a.w+b.w; return r;
}
__device__ __forceinline__ float4 f4clip(float4 a) {
    float4 r; r.x=clip100(a.x); r.y=clip100(a.y); r.z=clip100(a.z); r.w=clip100(a.w); return r;
}
// load 4 consecutive halfs (8B) -> float4
__device__ __forceinline__ float4 h4_to_f4(const __half2* p) {
    uint2 u = *(const uint2*)p;
    __half2 a = *(__half2*)&u.x;
    __half2 b = *(__half2*)&u.y;
    float2 fa = __half22float2(a);
    float2 fb = __half22float2(b);
    float4 r; r.x = fa.x; r.y = fa.y; r.z = fb.x; r.w = fb.y;
    return r;
}
__device__ __forceinline__ void f4_to_h4(float4 a, __half2* p) {
    __half2 h0 = __floats2half2_rn(a.x, a.y);
    __half2 h1 = __floats2half2_rn(a.z, a.w);
    uint2 u;
    u.x = *(uint32_t*)&h0;
    u.y = *(uint32_t*)&h1;
    *(uint2*)p = u;
}

__device__ __forceinline__ uint32_t smem_u32(const void* p) {
    uint32_t a;
    asm("{ .reg .u64 tmp; cvta.to.shared.u64 tmp, %1; cvt.u32.u64 %0, tmp; }"
        : "=r"(a) : "l"(p));
    return a;
}
__device__ __forceinline__ uint32_t cvt_bf2(float a, float b) {
    uint32_t r;
    asm("cvt.rn.bf16x2.f32 %0, %1, %2;" : "=r"(r) : "f"(b), "f"(a));
    return r;
}
__device__ __forceinline__ void split2(float a, float b, uint32_t& h, uint32_t& l) {
    h = cvt_bf2(a, b);
    float r0 = a - __uint_as_float(h << 16);
    float r1 = b - __uint_as_float(h & 0xFFFF0000u);
    l = cvt_bf2(r0, r1);
}
__device__ __forceinline__ void ldsm_x4(uint32_t* r, uint32_t addr) {
    asm volatile("ldmatrix.sync.aligned.m8n8.x4.shared.b16 {%0,%1,%2,%3}, [%4];"
                 : "=r"(r[0]), "=r"(r[1]), "=r"(r[2]), "=r"(r[3]) : "r"(addr));
}
__device__ __forceinline__ void mma_bf16(float* d, const uint32_t* a, uint32_t b0, uint32_t b1) {
    asm volatile("mma.sync.aligned.m16n8k16.row.col.f32.bf16.bf16.f32 "
        "{%0,%1,%2,%3}, {%4,%5,%6,%7}, {%8,%9}, {%0,%1,%2,%3};"
        : "+f"(d[0]), "+f"(d[1]), "+f"(d[2]), "+f"(d[3])
        : "r"(a[0]), "r"(a[1]), "r"(a[2]), "r"(a[3]), "r"(b0), "r"(b1));
}
#define SW128(o) ((o) ^ (((o) >> 3) & 0x70))

// ============================================================
// Weight pre-convert: W[K,N] fp32 -> Wt[N][K] bf16 hi/lo
// ============================================================
__global__ void k_convW(const float* __restrict__ W0, const float* __restrict__ W1,
                        const float* __restrict__ W2, const float* __restrict__ W3,
                        const float* __restrict__ W4) {
    const float* srcs[5] = {W0, W1, W2, W3, W4};
    const int Ks[5]   = {128, 128, 256, 128, 128};
    const int Ns[5]   = {128, 384, 128, 384, 256};
    const int offs[5] = {0, 16384, 65536, 98304, 147456};
    int w = blockIdx.y;
    const float* W = srcs[w];
    int K = Ks[w], N = Ns[w], off = offs[w];
    int total = K * N;
    for (int idx = blockIdx.x * blockDim.x + threadIdx.x; idx < total;
         idx += gridDim.x * blockDim.x) {
        int n = idx / K, k = idx - n * K;
        float v = W[k * N + n];
        __nv_bfloat16 h = __float2bfloat16(v);
        float r = v - __bfloat162float(h);
        g_whi[off + idx] = h;
        g_wlo[off + idx] = __float2bfloat16(r);
    }
}

// v fp32 -> fp16 copy (for message gathers)
__global__ void k_convV(const float* __restrict__ v) {
    long i = (long)blockIdx.x * blockDim.x + threadIdx.x;   // over N*96 float4 groups
    if (i >= (long)N_NODES * 96) return;
    float4 a = ((const float4*)v)[i];
    f4_to_h4(a, (__half2*)(g_vh + i * 4));
}

// ============================================================
// General split-bf16 mma.sync GEMM (R8-proven).
// OSPLIT: 1 = packed bf16 hi/lo (chi/clo), 2 = fp16 (C cast to __half*)
// ============================================================
#define MG_OFF_AHI   0
#define MG_OFF_ALO   16384
#define MG_OFF_BHI   32768
#define MG_OFF_BLO   49152
#define MG_SMEM_TOTAL 65536

template<int EPI, int ASPLIT, int OSPLIT>
__global__ __launch_bounds__(256, 2)
void k_mgemm(const float* __restrict__ A,
             const __nv_bfloat16* __restrict__ ahi_g, const __nv_bfloat16* __restrict__ alo_g,
             int woff, const float* __restrict__ bias,
             float* __restrict__ C, uint32_t* __restrict__ chi, uint32_t* __restrict__ clo,
             int M, int N, int K)
{
    extern __shared__ char smem[];
    const uint32_t sb = smem_u32(smem);

    const int t = threadIdx.x;
    const int lane = t & 31;
    const int wid = t >> 5;
    const int warp_m = wid & 3;
    const int warp_n = wid >> 2;
    const int m0 = blockIdx.x * 128;
    const int n0 = blockIdx.y * 128;

    const __nv_bfloat16* bhg = g_whi + woff;
    const __nv_bfloat16* blg = g_wlo + woff;

    float acc[2][8][4];
#pragma unroll
    for (int i = 0; i < 2; i++)
#pragma unroll
        for (int j = 0; j < 8; j++)
#pragma unroll
            for (int q = 0; q < 4; q++) acc[i][j][q] = 0.f;

    const int a_row  = warp_m * 32 + (lane & 15);
    const int a_atom = lane >> 4;
    const int b_row  = warp_n * 64 + (lane & 7) + ((lane & 16) ? 8 : 0);
    const int b_atom = (lane >> 3) & 1;

    const int nchunk = K >> 6;
    for (int c = 0; c < nchunk; c++) {
        const int k0 = c << 6;
        if (ASPLIT) {
#pragma unroll
            for (int i = 0; i < 4; i++) {
                int idx = t + i * 256;
                int row = idx >> 3;
                int kq  = idx & 7;
                uint4 h = make_uint4(0,0,0,0), l = make_uint4(0,0,0,0);
                if (m0 + row < M) {
                    long ga = (long)(m0 + row) * K + k0 + kq * 8;
                    h = *(const uint4*)(ahi_g + ga);
                    l = *(const uint4*)(alo_g + ga);
                }
                uint32_t off = SW128((uint32_t)(row * 128 + kq * 16));
                *(uint4*)(smem + MG_OFF_AHI + off) = h;
                *(uint4*)(smem + MG_OFF_ALO + off) = l;
            }
        } else {
#pragma unroll
            for (int i = 0; i < 8; i++) {
                int idx = t + i * 256;
                int row = idx >> 4;
                int kq  = idx & 15;
                float4 a = f4z();
                if (m0 + row < M) a = *(const float4*)(A + (long)(m0 + row) * K + k0 + kq * 4);
                uint32_t h0, l0, h1, l1;
                split2(a.x, a.y, h0, l0);
                split2(a.z, a.w, h1, l1);
                uint32_t off = SW128((uint32_t)(row * 128 + kq * 8));
                *(uint2*)(smem + MG_OFF_AHI + off) = make_uint2(h0, h1);
                *(uint2*)(smem + MG_OFF_ALO + off) = make_uint2(l0, l1);
            }
        }
#pragma unroll
        for (int i = 0; i < 4; i++) {
            int idx = t + i * 256;
            int row = idx >> 3;
            int kq  = idx & 7;
            long ga = (long)(n0 + row) * K + k0 + kq * 8;
            uint4 h = *(const uint4*)(bhg + ga);
            uint4 l = *(const uint4*)(blg + ga);
            uint32_t off = SW128((uint32_t)(row * 128 + kq * 16));
            *(uint4*)(smem + MG_OFF_BHI + off) = h;
            *(uint4*)(smem + MG_OFF_BLO + off) = l;
        }
        __syncthreads();
#pragma unroll
        for (int ks = 0; ks < 4; ks++) {
            uint32_t ahi[2][4], alo[2][4];
#pragma unroll
            for (int mt = 0; mt < 2; mt++) {
                uint32_t off = SW128((uint32_t)((a_row + mt * 16) * 128 + (ks * 2 + a_atom) * 16));
                ldsm_x4(ahi[mt], sb + MG_OFF_AHI + off);
                ldsm_x4(alo[mt], sb + MG_OFF_ALO + off);
            }
#pragma unroll
            for (int j = 0; j < 4; j++) {
                uint32_t offb = SW128((uint32_t)((b_row + j * 16) * 128 + (ks * 2 + b_atom) * 16));
                uint32_t bh[4], bl[4];
                ldsm_x4(bh, sb + MG_OFF_BHI + offb);
                ldsm_x4(bl, sb + MG_OFF_BLO + offb);
#pragma unroll
                for (int mt = 0; mt < 2; mt++) {
                    mma_bf16(acc[mt][2*j],   ahi[mt], bh[0], bh[1]);
                    mma_bf16(acc[mt][2*j],   alo[mt], bh[0], bh[1]);
                    mma_bf16(acc[mt][2*j],   ahi[mt], bl[0], bl[1]);
                    mma_bf16(acc[mt][2*j+1], ahi[mt], bh[2], bh[3]);
                    mma_bf16(acc[mt][2*j+1], alo[mt], bh[2], bh[3]);
                    mma_bf16(acc[mt][2*j+1], ahi[mt], bl[2], bl[3]);
                }
            }
        }
        __syncthreads();
    }

    const int g   = lane >> 2;
    const int tg2 = (lane & 3) * 2;
#pragma unroll
    for (int mt = 0; mt < 2; mt++) {
        int row = m0 + warp_m * 32 + mt * 16 + g;
#pragma unroll
        for (int nt = 0; nt < 8; nt++) {
            int col = n0 + warp_n * 64 + nt * 8 + tg2;
            float d0 = acc[mt][nt][0], d1 = acc[mt][nt][1];
            float d2 = acc[mt][nt][2], d3 = acc[mt][nt][3];
            if (EPI > 0) {
                float b0 = bias[col], b1 = bias[col + 1];
                d0 += b0; d1 += b1; d2 += b0; d3 += b1;
            }
            if (EPI == 2) {
                d0 = silu_f(d0); d1 = silu_f(d1); d2 = silu_f(d2); d3 = silu_f(d3);
            }
            if (OSPLIT == 1) {
                if (row < M) {
                    uint32_t h, l; split2(d0, d1, h, l);
                    long hx = ((long)row * N + col) >> 1;
                    chi[hx] = h; clo[hx] = l;
                }
                if (row + 8 < M) {
                    uint32_t h, l; split2(d2, d3, h, l);
                    long hx = ((long)(row + 8) * N + col) >> 1;
                    chi[hx] = h; clo[hx] = l;
                }
            } else {
                __half* Ch = (__half*)C;
                if (row < M) {
                    __half2 o = __floats2half2_rn(d0, d1);
                    *(__half2*)(Ch + (long)row * N + col) = o;
                }
                if (row + 8 < M) {
                    __half2 o = __floats2half2_rn(d2, d3);
                    *(__half2*)(Ch + (long)(row + 8) * N + col) = o;
                }
            }
        }
    }
}

// ============================================================
// vw GEMM: g_vwh[75000,256] (fp16) = out_v[75000,128] @ Wv
// ============================================================
#define VW_AHI(kc) ((kc) * 16384)
#define VW_ALO(kc) (32768 + (kc) * 16384)
#define VW_BHI 65536
#define VW_BLO 81920
#define VW_SMEM_TOTAL 98304

__global__ __launch_bounds__(256, 2)
void k_vw(const float* __restrict__ A, __half* __restrict__ C)
{
    const int M = N_NODES * 3, K = 128, N = 256;
    extern __shared__ char smem[];
    const uint32_t sb = smem_u32(smem);

    const int t = threadIdx.x;
    const int lane = t & 31;
    const int wid = t >> 5;
    const int warp_m = wid & 3;
    const int warp_n = wid >> 2;
    const int m0 = blockIdx.x * 128;

    const __nv_bfloat16* bhg = g_whi + 147456;
    const __nv_bfloat16* blg = g_wlo + 147456;

    const int a_row  = warp_m * 32 + (lane & 15);
    const int a_atom = lane >> 4;
    const int b_row  = warp_n * 64 + (lane & 7) + ((lane & 16) ? 8 : 0);
    const int b_atom = (lane >> 3) & 1;

#pragma unroll
    for (int i = 0; i < 16; i++) {
        int idx = t + i * 256;
        int row = idx >> 5;
        int kq4 = idx & 31;
        int kc  = kq4 >> 4;
        int kq  = kq4 & 15;
        float4 a = f4z();
        if (m0 + row < M) a = *(const float4*)(A + (long)(m0 + row) * K + kq4 * 4);
        uint32_t h0, l0, h1, l1;
        split2(a.x, a.y, h0, l0);
        split2(a.z, a.w, h1, l1);
        uint32_t off = SW128((uint32_t)(row * 128 + kq * 8));
        *(uint2*)(smem + VW_AHI(kc) + off) = make_uint2(h0, h1);
        *(uint2*)(smem + VW_ALO(kc) + off) = make_uint2(l0, l1);
    }
    __syncthreads();

    const int g   = lane >> 2;
    const int tg2 = (lane & 3) * 2;

#pragma unroll
    for (int nh = 0; nh < 2; nh++) {
        float acc[2][8][4];
#pragma unroll
        for (int i = 0; i < 2; i++)
#pragma unroll
            for (int j = 0; j < 8; j++)
#pragma unroll
                for (int q = 0; q < 4; q++) acc[i][j][q] = 0.f;

#pragma unroll
        for (int kc = 0; kc < 2; kc++) {
            if (!(nh == 0 && kc == 0)) __syncthreads();
#pragma unroll
            for (int i = 0; i < 4; i++) {
                int idx = t + i * 256;
                int row = idx >> 3;
                int kq  = idx & 7;
                long ga = (long)(nh * 128 + row) * K + kc * 64 + kq * 8;
                uint4 h = *(const uint4*)(bhg + ga);
                uint4 l = *(const uint4*)(blg + ga);
                uint32_t off = SW128((uint32_t)(row * 128 + kq * 16));
                *(uint4*)(smem + VW_BHI + off) = h;
                *(uint4*)(smem + VW_BLO + off) = l;
            }
            __syncthreads();
#pragma unroll
            for (int ks = 0; ks < 4; ks++) {
                uint32_t ahi[2][4], alo[2][4];
#pragma unroll
                for (int mt = 0; mt < 2; mt++) {
                    uint32_t off = SW128((uint32_t)((a_row + mt * 16) * 128 + (ks * 2 + a_atom) * 16));
                    ldsm_x4(ahi[mt], sb + VW_AHI(kc) + off);
                    ldsm_x4(alo[mt], sb + VW_ALO(kc) + off);
                }
#pragma unroll
                for (int j = 0; j < 4; j++) {
                    uint32_t offb = SW128((uint32_t)((b_row + j * 16) * 128 + (ks * 2 + b_atom) * 16));
                    uint32_t bh[4], bl[4];
                    ldsm_x4(bh, sb + VW_BHI + offb);
                    ldsm_x4(bl, sb + VW_BLO + offb);
#pragma unroll
                    for (int mt = 0; mt < 2; mt++) {
                        mma_bf16(acc[mt][2*j],   ahi[mt], bh[0], bh[1]);
                        mma_bf16(acc[mt][2*j],   alo[mt], bh[0], bh[1]);
                        mma_bf16(acc[mt][2*j],   ahi[mt], bl[0], bl[1]);
                        mma_bf16(acc[mt][2*j+1], ahi[mt], bh[2], bh[3]);
                        mma_bf16(acc[mt][2*j+1], alo[mt], bh[2], bh[3]);
                        mma_bf16(acc[mt][2*j+1], ahi[mt], bl[2], bl[3]);
                    }
                }
            }
        }
#pragma unroll
        for (int mt = 0; mt < 2; mt++) {
            int row = m0 + warp_m * 32 + mt * 16 + g;
#pragma unroll
            for (int nt = 0; nt < 8; nt++) {
                int col = nh * 128 + warp_n * 64 + nt * 8 + tg2;
                if (row < M) {
                    __half2 o = __floats2half2_rn(acc[mt][nt][0], acc[mt][nt][1]);
                    *(__half2*)(C + (long)row * N + col) = o;
                }
                if (row + 8 < M) {
                    __half2 o = __floats2half2_rn(acc[mt][nt][2], acc[mt][nt][3]);
                    *(__half2*)(C + (long)(row + 8) * N + col) = o;
                }
            }
        }
    }
}

// ============================================================
// CSR build by sender
// ============================================================
__global__ void k_count(const int* __restrict__ senders) {
    int e = blockIdx.x * blockDim.x + threadIdx.x;
    if (e < N_EDGES) atomicAdd(&g_cnt[senders[e]], 1);
}
__global__ void k_scanA() {
    __shared__ int sm[1024];
    int t = threadIdx.x;
    int i = blockIdx.x * 1024 + t;
    int v = (i < N_NODES) ? g_cnt[i] : 0;
    sm[t] = v;
    __syncthreads();
    for (int off = 1; off < 1024; off <<= 1) {
        int x = (t >= off) ? sm[t - off] : 0;
        __syncthreads();
        sm[t] += x;
        __syncthreads();
    }
    if (i < N_NODES) g_off[i] = sm[t] - v;
    if (t == 1023) g_bsum[blockIdx.x] = sm[1023];
}
__global__ void k_scanC() {
    __shared__ int pre_sh;
    if (threadIdx.x == 0) {
        int p = 0;
        for (int b = 0; b < blockIdx.x; b++) p += g_bsum[b];
        pre_sh = p;
        if (blockIdx.x == gridDim.x - 1) g_off[N_NODES] = p + g_bsum[blockIdx.x];
    }
    __syncthreads();
    int pre = pre_sh;
    int i = blockIdx.x * 1024 + threadIdx.x;
    if (i < N_NODES) {
        int o = g_off[i] + pre;
        g_off[i] = o;
        g_cur[i] = o;
    }
}
__global__ void k_fill(const int* __restrict__ senders, const int* __restrict__ receivers,
                       const float* __restrict__ dir_ij) {
    int e = blockIdx.x * blockDim.x + threadIdx.x;
    if (e < N_EDGES) {
        int p = atomicAdd(&g_cur[senders[e]], 1);
        float4 ed;
        ed.x = dir_ij[e * 3 + 0];
        ed.y = dir_ij[e * 3 + 1];
        ed.z = dir_ij[e * 3 + 2];
        ed.w = __int_as_float(e);
        g_edir[p] = ed;
        g_ercv[p] = receivers[e];
    }
}

// ============================================================
// Message gather-reduce: TWO warps per node (even/odd edge split).
// Wij evict-first; x/v gathered fp16. Partials combined via smem.
// ============================================================
__global__ void k_message(const float* __restrict__ s, const float* __restrict__ v,
                          const float* __restrict__ Wij,
                          float* __restrict__ out_s, float* __restrict__ out_v) {
    __shared__ float4 red[4][32][4];
    int gw   = (blockIdx.x * blockDim.x + threadIdx.x) >> 5;
    int node = gw >> 1;
    int half = gw & 1;
    int lane = threadIdx.x & 31;
    int pair = (threadIdx.x >> 6);
    if (node >= N_NODES) return;

    float4 ds  = f4z();
    float4 dv0 = f4z(), dv1 = f4z(), dv2 = f4z();

    int beg = g_off[node], end = g_off[node + 1];
    for (int i = beg + half; i < end; i += 2) {
        float4 ed = g_edir[i];
        int r = g_ercv[i];
        int e = __float_as_int(ed.w);
        const float4*  we = (const float4*)(Wij + (long)e * 384);
        const __half2* xr = (const __half2*)g_xh + (long)r * 192;
        const __half2* vr = (const __half2*)g_vh + (long)r * 192;

        float4 w0 = __ldcs(we + lane);
        float4 w1 = __ldcs(we + 32 + lane);
        float4 w2 = __ldcs(we + 64 + lane);
        float4 x0 = h4_to_f4(xr + lane * 2);
        float4 x1 = h4_to_f4(xr + 64 + lane * 2);
        float4 x2 = h4_to_f4(xr + 128 + lane * 2);

        ds = f4fma4(w0, x0, ds);
        float4 m1 = f4mul(w1, x1);
        float4 m2 = f4mul(w2, x2);

        float4 vj0 = h4_to_f4(vr + lane * 2);
        float4 vj1 = h4_to_f4(vr + 64 + lane * 2);
        float4 vj2 = h4_to_f4(vr + 128 + lane * 2);
        dv0 = f4fma(ed.x, m1, dv0); dv0 = f4fma4(m2, vj0, dv0);
        dv1 = f4fma(ed.y, m1, dv1); dv1 = f4fma4(m2, vj1, dv1);
        dv2 = f4fma(ed.z, m1, dv2); dv2 = f4fma4(m2, vj2, dv2);
    }

    if (half == 1) {
        red[pair][lane][0] = ds;
        red[pair][lane][1] = dv0;
        red[pair][lane][2] = dv1;
        red[pair][lane][3] = dv2;
    }
    __syncthreads();
    if (half == 0) {
        ds  = f4add(ds,  red[pair][lane][0]);
        dv0 = f4add(dv0, red[pair][lane][1]);
        dv1 = f4add(dv1, red[pair][lane][2]);
        dv2 = f4add(dv2, red[pair][lane][3]);

        float4 s4 = ((const float4*)(s + node * HDIM))[lane];
        ((float4*)(out_s + node * HDIM))[lane] = f4add(s4, f4clip(ds));

        const float4* vi = (const float4*)(v + (long)node * 384);
        float4* vo = (float4*)(out_v + (long)node * 384);
        vo[lane]      = f4add(vi[lane],      f4clip(dv0));
        vo[32 + lane] = f4add(vi[32 + lane], f4clip(dv1));
        vo[64 + lane] = f4add(vi[64 + lane], f4clip(dv2));
    }
}

// ============================================================
// Build ts (pre-split bf16 hi/lo) and dot (fp16) from g_vwh
// ============================================================
__global__ void k_ts(const float* __restrict__ out_s) {
    long idx = (long)blockIdx.x * blockDim.x + threadIdx.x;
    if (idx >= (long)N_NODES * 32) return;
    int n  = (int)(idx >> 5);
    int c4 = (int)(idx & 31);
    const __half2* vw = (const __half2*)(g_vwh + (long)n * 768);
    float4 vl0 = h4_to_f4(vw + c4 * 2),       vr0 = h4_to_f4(vw + 64 + c4 * 2);
    float4 vl1 = h4_to_f4(vw + 128 + c4 * 2), vr1 = h4_to_f4(vw + 192 + c4 * 2);
    float4 vl2 = h4_to_f4(vw + 256 + c4 * 2), vr2 = h4_to_f4(vw + 320 + c4 * 2);
    float4 vn;
    vn.x = sqrtf(vr0.x*vr0.x + vr1.x*vr1.x + vr2.x*vr2.x + 1e-8f);
    vn.y = sqrtf(vr0.y*vr0.y + vr1.y*vr1.y + vr2.y*vr2.y + 1e-8f);
    vn.z = sqrtf(vr0.z*vr0.z + vr1.z*vr1.z + vr2.z*vr2.z + 1e-8f);
    vn.w = sqrtf(vr0.w*vr0.w + vr1.w*vr1.w + vr2.w*vr2.w + 1e-8f);

    float4 sv = ((const float4*)(out_s + (long)n * 128))[c4];
    long hb = (long)n * 128 + c4 * 2;
    uint32_t h0, l0, h1, l1;
    split2(sv.x, sv.y, h0, l0);
    split2(sv.z, sv.w, h1, l1);
    *(uint2*)(g_tshi + hb) = make_uint2(h0, h1);
    *(uint2*)(g_tslo + hb) = make_uint2(l0, l1);
    split2(vn.x, vn.y, h0, l0);
    split2(vn.z, vn.w, h1, l1);
    *(uint2*)(g_tshi + hb + 64) = make_uint2(h0, h1);
    *(uint2*)(g_tslo + hb + 64) = make_uint2(l0, l1);

    float4 dt;
    dt.x = vr0.x*vl0.x + vr1.x*vl1.x + vr2.x*vl2.x;
    dt.y = vr0.y*vl0.y + vr1.y*vl1.y + vr2.y*vl2.y;
    dt.z = vr0.z*vl0.z + vr1.z*vl1.z + vr2.z*vl2.z;
    dt.w = vr0.w*vl0.w + vr1.w*vl1.w + vr2.w*vl2.w;
    f4_to_h4(dt, (__half2*)(g_doth + idx * 4));
}

// ============================================================
// Final epilogue (reads O, dot, vw as fp16)
// ============================================================
__global__ void k_final(float* __restrict__ out_s, float* __restrict__ out_v) {
    long idx = (long)blockIdx.x * blockDim.x + threadIdx.x;
    if (idx >= (long)N_NODES * 32) return;
    int n  = (int)(idx >> 5);
    int c4 = (int)(idx & 31);
    const __half2* O = (const __half2*)(g_oh + (long)n * 384);
    float4 o0 = h4_to_f4(O + c4 * 2);
    float4 o1 = h4_to_f4(O + 64 + c4 * 2);
    float4 o2 = h4_to_f4(O + 128 + c4 * 2);
    float4 dot = h4_to_f4((const __half2*)(g_doth + idx * 4));
    float4 sacc = ((float4*)out_s)[idx];
    sacc.x += clip100(fmaf(o2.x, dot.x, o0.x));
    sacc.y += clip100(fmaf(o2.y, dot.y, o0.y));
    sacc.z += clip100(fmaf(o2.z, dot.z, o0.z));
    sacc.w += clip100(fmaf(o2.w, dot.w, o0.w));
    ((float4*)out_s)[idx] = sacc;
    const __half2* vw = (const __half2*)(g_vwh + (long)n * 768);
    float4* vv = (float4*)(out_v + (long)n * 384);
#pragma unroll
    for (int d = 0; d < 3; d++) {
        float4 vl = h4_to_f4(vw + d * 128 + c4 * 2);
        float4 acc = vv[d * 32 + c4];
        acc.x += clip100(vl.x * o1.x);
        acc.y += clip100(vl.y * o1.y);
        acc.z += clip100(vl.z * o1.z);
        acc.w += clip100(vl.w * o1.w);
        vv[d * 32 + c4] = acc;
    }
}

// ============================================================
extern "C" void kernel_launch(void* const* d_in, const int* in_sizes, int n_in,
                              void* d_out, int out_size) {
    const float* s   = (const float*)d_in[0];
    const float* v   = (const float*)d_in[1];
    const float* dir = (const float*)d_in[2];
    const float* Wij = (const float*)d_in[3];
    const float* Wi1 = (const float*)d_in[4];
    const float* bi1 = (const float*)d_in[5];
    const float* Wi2 = (const float*)d_in[6];
    const float* bi2 = (const float*)d_in[7];
    const float* Wm1 = (const float*)d_in[8];
    const float* bm1 = (const float*)d_in[9];
    const float* Wm2 = (const float*)d_in[10];
    const float* bm2 = (const float*)d_in[11];
    const float* Wv  = (const float*)d_in[12];
    const int*   snd = (const int*)d_in[13];
    const int*   rcv = (const int*)d_in[14];

    float* out_s = (float*)d_out;
    float* out_v = (float*)d_out + (long)N_NODES * HDIM;

    __half*   p_xh;   cudaGetSymbolAddress((void**)&p_xh,   g_xh);
    __half*   p_oh;   cudaGetSymbolAddress((void**)&p_oh,   g_oh);
    __half*   p_vwh;  cudaGetSymbolAddress((void**)&p_vwh,  g_vwh);
    uint32_t* p_hhi;  cudaGetSymbolAddress((void**)&p_hhi,  g_hhi);
    uint32_t* p_hlo;  cudaGetSymbolAddress((void**)&p_hlo,  g_hlo);
    uint32_t* p_tshi; cudaGetSymbolAddress((void**)&p_tshi, g_tshi);
    uint32_t* p_tslo; cudaGetSymbolAddress((void**)&p_tslo, g_tslo);
    uint32_t* p_hmhi; cudaGetSymbolAddress((void**)&p_hmhi, g_hmhi);
    uint32_t* p_hmlo; cudaGetSymbolAddress((void**)&p_hmlo, g_hmlo);
    int*      p_cnt;  cudaGetSymbolAddress((void**)&p_cnt,  g_cnt);

    static cudaStream_t s2 = nullptr;
    static cudaEvent_t  e1 = nullptr, e2 = nullptr;
    if (!s2) {
        cudaStreamCreateWithFlags(&s2, cudaStreamNonBlocking);
        cudaEventCreateWithFlags(&e1, cudaEventDisableTiming);
        cudaEventCreateWithFlags(&e2, cudaEventDisableTiming);
        cudaFuncSetAttribute(k_mgemm<2,0,1>, cudaFuncAttributeMaxDynamicSharedMemorySize, MG_SMEM_TOTAL);
        cudaFuncSetAttribute(k_mgemm<1,1,2>, cudaFuncAttributeMaxDynamicSharedMemorySize, MG_SMEM_TOTAL);
        cudaFuncSetAttribute(k_mgemm<2,1,1>, cudaFuncAttributeMaxDynamicSharedMemorySize, MG_SMEM_TOTAL);
        cudaFuncSetAttribute(k_vw, cudaFuncAttributeMaxDynamicSharedMemorySize, VW_SMEM_TOTAL);
    }

    const int TPB = 256;
    int edge_blocks = (N_EDGES + TPB - 1) / TPB;
    int msg_blocks  = (int)(((long)N_NODES * 64 + TPB - 1) / TPB);   // 2 warps/node
    int nc4_blocks = (int)(((long)N_NODES * 32 + TPB - 1) / TPB);
    int nv4_blocks = (int)(((long)N_NODES * 96 + TPB - 1) / TPB);
    const int MB  = (N_NODES + 127) / 128;        // 196
    const int MB3 = (N_NODES * 3 + 127) / 128;    // 586
    const int SCAN_BLK = (N_NODES + 1023) / 1024; // 25

    // ---- fork: v fp16 conv + CSR build on s2, concurrent with MLP GEMMs ----
    cudaEventRecord(e1, 0);
    cudaStreamWaitEvent(s2, e1, 0);
    k_convV<<<nv4_blocks, TPB, 0, s2>>>(v);
    cudaMemsetAsync(p_cnt, 0, N_NODES * sizeof(int), s2);
    k_count<<<edge_blocks, TPB, 0, s2>>>(snd);
    k_scanA<<<SCAN_BLK, 1024, 0, s2>>>();
    k_scanC<<<SCAN_BLK, 1024, 0, s2>>>();
    k_fill<<<edge_blocks, TPB, 0, s2>>>(snd, rcv, dir);
    cudaEventRecord(e2, s2);

    // ---- main stream: node MLP (x written as fp16) ----
    k_convW<<<dim3(64, 5), TPB>>>(Wi1, Wi2, Wm1, Wm2, Wv);
    k_mgemm<2,0,1><<<dim3(MB, 1), 256, MG_SMEM_TOTAL>>>(
        s, (const __nv_bfloat16*)0, (const __nv_bfloat16*)0, 0, bi1,
        (float*)0, p_hhi, p_hlo, N_NODES, 128, 128);
    k_mgemm<1,1,2><<<dim3(MB, 3), 256, MG_SMEM_TOTAL>>>(
        (const float*)0, (const __nv_bfloat16*)p_hhi, (const __nv_bfloat16*)p_hlo, 16384, bi2,
        (float*)p_xh, (uint32_t*)0, (uint32_t*)0, N_NODES, 384, 128);

    // ---- join, then message ----
    cudaStreamWaitEvent(0, e2, 0);
    k_message<<<msg_blocks, TPB>>>(s, v, Wij, out_s, out_v);

    // ---- update phase ----
    k_vw<<<MB3, 256, VW_SMEM_TOTAL>>>(out_v, p_vwh);
    k_ts<<<nc4_blocks, TPB>>>(out_s);
    k_mgemm<2,1,1><<<dim3(MB, 1), 256, MG_SMEM_TOTAL>>>(
        (const float*)0, (const __nv_bfloat16*)p_tshi, (const __nv_bfloat16*)p_tslo, 65536, bm1,
        (float*)0, p_hmhi, p_hmlo, N_NODES, 128, 256);
    k_mgemm<1,1,2><<<dim3(MB, 3), 256, MG_SMEM_TOTAL>>>(
        (const float*)0, (const __nv_bfloat16*)p_hmhi, (const __nv_bfloat16*)p_hmlo, 98304, bm2,
        (float*)p_oh, (uint32_t*)0, (uint32_t*)0, N_NODES, 384, 128);
    k_final<<<nc4_blocks, TPB>>>(out_s, out_v);
}